// round 4
// baseline (speedup 1.0000x reference)
#include <cuda_runtime.h>
#include <math.h>
#include <stdint.h>

#define N_NODES 10000
#define N_EDGES 160000
#define N_GRAPHS 64
#define T_TOW 5
#define FI 75
#define FO 15
#define N_LAYERS 4
#define MSG_DIM 375        // T*FI
#define MIN_DIM 225        // 3*FI
#define OUT_DIM 975        // 13*FI
#define POST_DIM 75        // T*FO
#define HCK 1600           // padded K for hc GEMM (1500 agg + 75 h + 25 pad)
#define HCN 225            // 3*75 output cols (raw | amp | att)
#define AVG_DEG_LOG 2.8332133440562162f

// ---------------- scratch ----------------------------------------------------
__device__ float d_h[N_NODES * FI];
__device__ float d_hc[N_NODES * FI];
__device__ float d_msgs[N_EDGES * MSG_DIM];        // msgs in CSR edge order
__device__ float d_agg[N_NODES * T_TOW * 4 * FI];  // [N,1500] contiguous
__device__ float d_G[N_NODES * HCN];               // hc GEMM output [N,225]
__device__ float d_Wt[MIN_DIM * MSG_DIM];          // pre_W[l] transposed [225,375]
__device__ float d_WB2[HCK * HCN];                 // hc GEMM B matrix [1600,225]
__device__ float d_bias2[FI];
__device__ float d_enctab[16 * FI];
__device__ int   d_cnt[N_NODES];
__device__ int   d_rowstart[N_NODES + 1];
__device__ int   d_cursor[N_NODES];
__device__ int   d_src_csr[N_EDGES];
__device__ int   d_dst_csr[N_EDGES];
__device__ int   d_combo_csr[N_EDGES];
__device__ float d_bnsum[FI];
__device__ float d_bnsq[FI];
__device__ float d_pool[N_GRAPHS * FI];

__device__ __forceinline__ float tf32r(float v) {
    uint32_t o;
    asm("cvt.rna.tf32.f32 %0, %1;" : "=r"(o) : "f"(v));
    return __uint_as_float(o);
}

__device__ __forceinline__ void mma_tf32(float* c, const uint32_t* a, const uint32_t* b) {
    asm volatile(
        "mma.sync.aligned.m16n8k8.row.col.f32.tf32.tf32.f32 "
        "{%0,%1,%2,%3}, {%4,%5,%6,%7}, {%8,%9}, {%0,%1,%2,%3};"
        : "+f"(c[0]), "+f"(c[1]), "+f"(c[2]), "+f"(c[3])
        : "r"(a[0]), "r"(a[1]), "r"(a[2]), "r"(a[3]), "r"(b[0]), "r"(b[1]));
}

// ---------------- h0 ----------------------------------------------------------
__global__ void k_h0(const int* __restrict__ x, const float* __restrict__ node_emb,
                     const float* __restrict__ W, const float* __restrict__ b) {
    int idx = blockIdx.x * blockDim.x + threadIdx.x;
    if (idx >= N_NODES * FI) return;
    int n = idx / FI, f = idx % FI;
    int i0 = x[n * 2 + 0], i1 = x[n * 2 + 1];
    const float* e0 = node_emb + i0 * FI;
    const float* e1 = node_emb + i1 * FI;
    float acc = b[f];
    #pragma unroll 5
    for (int c = 0; c < FI; c++) acc += e0[c] * W[c * FI + f];
    #pragma unroll 5
    for (int c = 0; c < FI; c++) acc += e1[c] * W[(FI + c) * FI + f];
    d_h[idx] = acc;
}

// ---------------- CSR build ---------------------------------------------------
__global__ void k_zero_cnt() {
    int i = blockIdx.x * blockDim.x + threadIdx.x;
    if (i < N_NODES) d_cnt[i] = 0;
}

__global__ void k_count(const int* __restrict__ edge_index) {
    int e = blockIdx.x * blockDim.x + threadIdx.x;
    if (e >= N_EDGES) return;
    atomicAdd(&d_cnt[edge_index[N_EDGES + e]], 1);
}

__global__ void k_scan() {
    __shared__ int ssum[1024];
    int tid = threadIdx.x;
    const int ITEMS = 10;
    int base = tid * ITEMS;
    int local[ITEMS];
    int s = 0;
    #pragma unroll
    for (int i = 0; i < ITEMS; i++) {
        int g = base + i;
        int v = (g < N_NODES) ? d_cnt[g] : 0;
        local[i] = s;
        s += v;
    }
    ssum[tid] = s;
    __syncthreads();
    for (int off = 1; off < 1024; off <<= 1) {
        int v = (tid >= off) ? ssum[tid - off] : 0;
        __syncthreads();
        ssum[tid] += v;
        __syncthreads();
    }
    int excl = (tid == 0) ? 0 : ssum[tid - 1];
    #pragma unroll
    for (int i = 0; i < ITEMS; i++) {
        int g = base + i;
        if (g < N_NODES) {
            int rs = excl + local[i];
            d_rowstart[g] = rs;
            d_cursor[g]   = rs;
        }
    }
    if (tid == 0) d_rowstart[N_NODES] = ssum[1023];
}

__global__ void k_fill(const int* __restrict__ edge_index, const int* __restrict__ edge_attr) {
    int e = blockIdx.x * blockDim.x + threadIdx.x;
    if (e >= N_EDGES) return;
    int dst = edge_index[N_EDGES + e];
    int pos = atomicAdd(&d_cursor[dst], 1);
    d_src_csr[pos]   = edge_index[e];
    d_dst_csr[pos]   = dst;
    d_combo_csr[pos] = edge_attr[e * 2] * 4 + edge_attr[e * 2 + 1];
}

// ---------------- per-layer prep ------------------------------------------------
__global__ void k_enctab(const float* __restrict__ edge_emb,
                         const float* __restrict__ encW, const float* __restrict__ encb) {
    int idx = blockIdx.x * blockDim.x + threadIdx.x;
    if (idx >= 16 * FI) return;
    int combo = idx / FI, f = idx % FI;
    int a0 = combo >> 2, a1 = combo & 3;
    const float* e0 = edge_emb + a0 * 25;
    const float* e1 = edge_emb + a1 * 25;
    float acc = encb[f];
    #pragma unroll 5
    for (int q = 0; q < 25; q++) acc += e0[q] * encW[q * FI + f];
    #pragma unroll 5
    for (int q = 0; q < 25; q++) acc += e1[q] * encW[(25 + q) * FI + f];
    d_enctab[idx] = acc;
}

__global__ void k_transpose(const float* __restrict__ preW) {
    int idx = blockIdx.x * blockDim.x + threadIdx.x;
    if (idx >= MIN_DIM * MSG_DIM) return;
    int c = idx / MSG_DIM, j = idx % MSG_DIM;
    int t = j / FI, f = j % FI;
    d_Wt[idx] = preW[(t * MIN_DIM + c) * FI + f];
}

// Build d_WB2[1600,225]:
//  k in [0,1500): t=k/300, k300=k%300; col j -> sel=j/75, jj=j%75;
//      c = 75 + sel*300 + k300;   WB2[k][j] = sum_f postW[t][c][f]*linW[t*15+f][jj]
//  k in [1500,1575): c = k-1500; j<75: sum_t sum_f postW[t][c][f]*linW[t*15+f][j]; else 0
//  k >= 1575: 0
__global__ void k_wb2(const float* __restrict__ postW, const float* __restrict__ linW) {
    int idx = blockIdx.x * blockDim.x + threadIdx.x;
    if (idx >= HCK * HCN) return;
    int k = idx / HCN, j = idx % HCN;
    float acc = 0.f;
    if (k < 1500) {
        int t = k / 300, k300 = k % 300;
        int sel = j / FI, jj = j % FI;
        int c = FI + sel * 300 + k300;
        const float* pw = postW + ((size_t)t * OUT_DIM + c) * FO;
        const float* lw = linW + (t * FO) * FI + jj;
        #pragma unroll
        for (int f = 0; f < FO; f++) acc += pw[f] * lw[f * FI];
    } else if (k < 1575 && j < FI) {
        int c = k - 1500;
        #pragma unroll
        for (int t = 0; t < T_TOW; t++) {
            const float* pw = postW + ((size_t)t * OUT_DIM + c) * FO;
            const float* lw = linW + (t * FO) * FI + j;
            #pragma unroll
            for (int f = 0; f < FO; f++) acc += pw[f] * lw[f * FI];
        }
    }
    d_WB2[idx] = acc;
}

__global__ void k_bias2(const float* __restrict__ postb, const float* __restrict__ linW,
                        const float* __restrict__ linb) {
    int j = threadIdx.x;
    if (j >= FI) return;
    float acc = linb[j];
    #pragma unroll 5
    for (int q = 0; q < T_TOW * FO; q++) acc += postb[q] * linW[q * FI + j];
    d_bias2[j] = acc;
}

__global__ void k_bnzero() {
    int i = threadIdx.x;
    if (i < FI) { d_bnsum[i] = 0.f; d_bnsq[i] = 0.f; }
}

// ---------------- msg GEMM: tf32 mma, fused gather, CSR order -------------------
__global__ void __launch_bounds__(256, 2) k_gemm_msg(const float* __restrict__ bias) {
    const int BM = 128, BN = 128;
    const int AS = 84, BS = 136;
    __shared__ float As[BM * AS];
    __shared__ float Bs[80 * BS];
    __shared__ int s_off[3][BM];

    int tid = threadIdx.x;
    int row0 = blockIdx.y * BM;
    int col0 = blockIdx.x * BN;
    int lane = tid & 31, warp = tid >> 5;
    int wm = (warp >> 2) * 64;
    int wn = (warp & 3) * 32;
    int g = lane >> 2, tc = lane & 3;

    if (tid < BM) {
        int r = row0 + tid;
        s_off[0][tid] = d_dst_csr[r] * FI;
        s_off[1][tid] = d_src_csr[r] * FI;
        s_off[2][tid] = d_combo_csr[r] * FI;
    }

    float acc[4][4][4];
    #pragma unroll
    for (int i = 0; i < 4; i++)
        #pragma unroll
        for (int j = 0; j < 4; j++)
            #pragma unroll
            for (int q = 0; q < 4; q++) acc[i][j][q] = 0.f;

    __syncthreads();

    for (int seg = 0; seg < 3; seg++) {
        const float* abase = (seg < 2) ? d_h : d_enctab;
        const int* offarr = s_off[seg];
        #pragma unroll
        for (int i = 0; i < 40; i++) {
            int idx = i * 256 + tid;
            int r = idx / 80, c = idx - r * 80;
            float v = (c < FI) ? abase[offarr[r] + c] : 0.f;
            As[r * AS + c] = tf32r(v);
        }
        #pragma unroll
        for (int i = 0; i < 40; i++) {
            int idx = i * 256 + tid;
            int kr = idx >> 7, c = idx & 127;
            int j = col0 + c;
            float v = (kr < FI && j < MSG_DIM) ? d_Wt[(seg * FI + kr) * MSG_DIM + j] : 0.f;
            Bs[kr * BS + c] = tf32r(v);
        }
        __syncthreads();
        #pragma unroll
        for (int kk = 0; kk < 80; kk += 8) {
            uint32_t a[4][4], b[4][2];
            #pragma unroll
            for (int i = 0; i < 4; i++) {
                int m = wm + i * 16 + g;
                a[i][0] = __float_as_uint(As[m * AS + kk + tc]);
                a[i][1] = __float_as_uint(As[(m + 8) * AS + kk + tc]);
                a[i][2] = __float_as_uint(As[m * AS + kk + tc + 4]);
                a[i][3] = __float_as_uint(As[(m + 8) * AS + kk + tc + 4]);
            }
            #pragma unroll
            for (int j = 0; j < 4; j++) {
                int n = wn + j * 8 + g;
                b[j][0] = __float_as_uint(Bs[(kk + tc) * BS + n]);
                b[j][1] = __float_as_uint(Bs[(kk + tc + 4) * BS + n]);
            }
            #pragma unroll
            for (int i = 0; i < 4; i++)
                #pragma unroll
                for (int j = 0; j < 4; j++) mma_tf32(acc[i][j], a[i], b[j]);
        }
        __syncthreads();
    }

    #pragma unroll
    for (int i = 0; i < 4; i++) {
        int r = row0 + wm + i * 16 + g;
        #pragma unroll
        for (int j = 0; j < 4; j++) {
            int cb = col0 + wn + j * 8 + 2 * tc;
            if (cb < MSG_DIM) {
                float b0 = bias[cb];
                d_msgs[(size_t)r * MSG_DIM + cb] = acc[i][j][0] + b0;
                d_msgs[(size_t)(r + 8) * MSG_DIM + cb] = acc[i][j][2] + b0;
                if (cb + 1 < MSG_DIM) {
                    float b1 = bias[cb + 1];
                    d_msgs[(size_t)r * MSG_DIM + cb + 1] = acc[i][j][1] + b1;
                    d_msgs[(size_t)(r + 8) * MSG_DIM + cb + 1] = acc[i][j][3] + b1;
                }
            }
        }
    }
}

// ---------------- segment reduce (msgs in CSR order) ----------------------------
__global__ void k_agg() {
    int n = blockIdx.x;
    int j = threadIdx.x;
    if (j >= MSG_DIM) return;
    int s0 = d_rowstart[n], s1 = d_rowstart[n + 1];
    float s = 0.f, sq = 0.f, mn = 3.4e38f, mx = -3.4e38f;
    for (int i = s0; i < s1; i++) {
        float v = d_msgs[(size_t)i * MSG_DIM + j];
        s += v; sq += v * v;
        mn = fminf(mn, v); mx = fmaxf(mx, v);
    }
    float cnt = (float)(s1 - s0);
    float deg = fmaxf(cnt, 1.f);
    float mean = s / deg;
    float var = sq / deg - mean * mean;
    if (var < 0.f) var = 0.f;
    float stdv = sqrtf(var + 1e-5f);
    if (s1 == s0) { mn = 0.f; mx = 0.f; }
    int t = j / FI, f = j % FI;
    float* a = d_agg + (size_t)n * (T_TOW * 4 * FI) + t * (4 * FI);
    a[f]          = mean;
    a[FI + f]     = mn;
    a[2 * FI + f] = mx;
    a[3 * FI + f] = stdv;
}

// ---------------- hc GEMM: G[10000,225] = A'[10000,1600] @ WB2[1600,225] --------
// A'[n, c] = c<1500 ? aggF[n,c] : (c<1575 ? h[n,c-1500] : 0)
__global__ void __launch_bounds__(256, 2) k_gemm_hc() {
    const int BM = 128, BN = 128;
    const int AS = 84, BS = 136;
    __shared__ float As[BM * AS];
    __shared__ float Bs[80 * BS];

    int tid = threadIdx.x;
    int row0 = blockIdx.y * BM;
    int col0 = blockIdx.x * BN;
    int lane = tid & 31, warp = tid >> 5;
    int wm = (warp >> 2) * 64;
    int wn = (warp & 3) * 32;
    int g = lane >> 2, tc = lane & 3;

    float acc[4][4][4];
    #pragma unroll
    for (int i = 0; i < 4; i++)
        #pragma unroll
        for (int j = 0; j < 4; j++)
            #pragma unroll
            for (int q = 0; q < 4; q++) acc[i][j][q] = 0.f;

    for (int k0 = 0; k0 < HCK; k0 += 80) {
        #pragma unroll
        for (int i = 0; i < 40; i++) {
            int idx = i * 256 + tid;
            int r = idx / 80, c = idx - r * 80;
            int grow = row0 + r;
            int gc = k0 + c;
            float v = 0.f;
            if (grow < N_NODES) {
                if (gc < 1500) v = d_agg[(size_t)grow * 1500 + gc];
                else if (gc < 1575) v = d_h[grow * FI + (gc - 1500)];
            }
            As[r * AS + c] = tf32r(v);
        }
        #pragma unroll
        for (int i = 0; i < 40; i++) {
            int idx = i * 256 + tid;
            int kr = idx >> 7, c = idx & 127;
            int j = col0 + c;
            float v = (j < HCN) ? d_WB2[(size_t)(k0 + kr) * HCN + j] : 0.f;
            Bs[kr * BS + c] = tf32r(v);
        }
        __syncthreads();
        #pragma unroll
        for (int kk = 0; kk < 80; kk += 8) {
            uint32_t a[4][4], b[4][2];
            #pragma unroll
            for (int i = 0; i < 4; i++) {
                int m = wm + i * 16 + g;
                a[i][0] = __float_as_uint(As[m * AS + kk + tc]);
                a[i][1] = __float_as_uint(As[(m + 8) * AS + kk + tc]);
                a[i][2] = __float_as_uint(As[m * AS + kk + tc + 4]);
                a[i][3] = __float_as_uint(As[(m + 8) * AS + kk + tc + 4]);
            }
            #pragma unroll
            for (int j = 0; j < 4; j++) {
                int n = wn + j * 8 + g;
                b[j][0] = __float_as_uint(Bs[(kk + tc) * BS + n]);
                b[j][1] = __float_as_uint(Bs[(kk + tc + 4) * BS + n]);
            }
            #pragma unroll
            for (int i = 0; i < 4; i++)
                #pragma unroll
                for (int j = 0; j < 4; j++) mma_tf32(acc[i][j], a[i], b[j]);
        }
        __syncthreads();
    }

    #pragma unroll
    for (int i = 0; i < 4; i++) {
        int r = row0 + wm + i * 16 + g;
        #pragma unroll
        for (int j = 0; j < 4; j++) {
            int cb = col0 + wn + j * 8 + 2 * tc;
            if (cb < HCN) {
                if (r < N_NODES) {
                    d_G[(size_t)r * HCN + cb] = acc[i][j][0];
                    if (cb + 1 < HCN) d_G[(size_t)r * HCN + cb + 1] = acc[i][j][1];
                }
                if (r + 8 < N_NODES) {
                    d_G[(size_t)(r + 8) * HCN + cb] = acc[i][j][2];
                    if (cb + 1 < HCN) d_G[(size_t)(r + 8) * HCN + cb + 1] = acc[i][j][3];
                }
            }
        }
    }
}

// ---------------- combine G -> hc + BN stats --------------------------------------
__global__ void k_combine() {
    __shared__ float ssum[FI], ssq[FI];
    int tid = threadIdx.x;
    if (tid < FI) { ssum[tid] = 0.f; ssq[tid] = 0.f; }
    __syncthreads();
    int base = blockIdx.x * 100;
    for (int idx = tid; idx < 100 * FI; idx += blockDim.x) {
        int n = base + idx / FI, f = idx % FI;
        float cnt = (float)(d_rowstart[n + 1] - d_rowstart[n]);
        float log_deg = logf(fmaxf(cnt, 1.f) + 1.f);
        float amp = log_deg / AVG_DEG_LOG;
        float att = AVG_DEG_LOG / log_deg;
        const float* gr = d_G + (size_t)n * HCN;
        float v = gr[f] + amp * gr[FI + f] + att * gr[2 * FI + f] + d_bias2[f];
        d_hc[n * FI + f] = v;
        atomicAdd(&ssum[f], v);
        atomicAdd(&ssq[f], v * v);
    }
    __syncthreads();
    if (tid < FI) {
        atomicAdd(&d_bnsum[tid], ssum[tid]);
        atomicAdd(&d_bnsq[tid], ssq[tid]);
    }
}

__global__ void k_bn(const float* __restrict__ g, const float* __restrict__ b) {
    int idx = blockIdx.x * blockDim.x + threadIdx.x;
    if (idx >= N_NODES * FI) return;
    int f = idx % FI;
    float mu = d_bnsum[f] / (float)N_NODES;
    float var = d_bnsq[f] / (float)N_NODES - mu * mu;
    float v = (d_hc[idx] - mu) * rsqrtf(var + 1e-5f) * g[f] + b[f];
    d_h[idx] = fmaxf(v, 0.f);
}

// ---------------- pool + MLP -----------------------------------------------------
__global__ void k_poolzero() {
    int i = blockIdx.x * blockDim.x + threadIdx.x;
    if (i < N_GRAPHS * FI) d_pool[i] = 0.f;
}

__global__ void k_pool(const int* __restrict__ batch) {
    int idx = blockIdx.x * blockDim.x + threadIdx.x;
    if (idx >= N_NODES * FI) return;
    int n = idx / FI, f = idx % FI;
    atomicAdd(&d_pool[batch[n] * FI + f], d_h[idx]);
}

__global__ void k_mlp(const float* __restrict__ W1, const float* __restrict__ b1,
                      const float* __restrict__ W2, const float* __restrict__ b2,
                      const float* __restrict__ W3, const float* __restrict__ b3,
                      float* __restrict__ out) {
    __shared__ float g[FI], h1[50], h2[25];
    int gi = blockIdx.x;
    int tid = threadIdx.x;
    if (tid < FI) g[tid] = d_pool[gi * FI + tid];
    __syncthreads();
    if (tid < 50) {
        float a = b1[tid];
        for (int c = 0; c < FI; c++) a += g[c] * W1[c * 50 + tid];
        h1[tid] = fmaxf(a, 0.f);
    }
    __syncthreads();
    if (tid < 25) {
        float a = b2[tid];
        for (int c = 0; c < 50; c++) a += h1[c] * W2[c * 25 + tid];
        h2[tid] = fmaxf(a, 0.f);
    }
    __syncthreads();
    if (tid == 0) {
        float a = b3[0];
        for (int c = 0; c < 25; c++) a += h2[c] * W3[c];
        out[gi] = a;
    }
}

// ---------------- launch -----------------------------------------------------------
extern "C" void kernel_launch(void* const* d_in, const int* in_sizes, int n_in,
                              void* d_out, int out_size) {
    const int*   x          = (const int*)d_in[0];
    const int*   edge_index = (const int*)d_in[1];
    const int*   edge_attr  = (const int*)d_in[2];
    const int*   batch      = (const int*)d_in[3];
    const float* node_emb   = (const float*)d_in[4];
    const float* edge_emb   = (const float*)d_in[5];
    const float* pre_lin_W  = (const float*)d_in[6];
    const float* pre_lin_b  = (const float*)d_in[7];
    const float* edge_enc_W = (const float*)d_in[8];
    const float* edge_enc_b = (const float*)d_in[9];
    const float* pre_W      = (const float*)d_in[10];
    const float* pre_b      = (const float*)d_in[11];
    const float* post_W     = (const float*)d_in[12];
    const float* post_b     = (const float*)d_in[13];
    const float* lin_W      = (const float*)d_in[14];
    const float* lin_b      = (const float*)d_in[15];
    const float* bn_g       = (const float*)d_in[16];
    const float* bn_b       = (const float*)d_in[17];
    const float* mlp_W1     = (const float*)d_in[18];
    const float* mlp_b1     = (const float*)d_in[19];
    const float* mlp_W2     = (const float*)d_in[20];
    const float* mlp_b2     = (const float*)d_in[21];
    const float* mlp_W3     = (const float*)d_in[22];
    const float* mlp_b3     = (const float*)d_in[23];
    float* out = (float*)d_out;

    k_h0<<<(N_NODES * FI + 255) / 256, 256>>>(x, node_emb, pre_lin_W, pre_lin_b);

    k_zero_cnt<<<(N_NODES + 255) / 256, 256>>>();
    k_count<<<(N_EDGES + 255) / 256, 256>>>(edge_index);
    k_scan<<<1, 1024>>>();
    k_fill<<<(N_EDGES + 255) / 256, 256>>>(edge_index, edge_attr);

    for (int l = 0; l < N_LAYERS; l++) {
        k_enctab<<<(16 * FI + 255) / 256, 256>>>(edge_emb,
            edge_enc_W + l * 50 * FI, edge_enc_b + l * FI);
        k_transpose<<<(MIN_DIM * MSG_DIM + 255) / 256, 256>>>(
            pre_W + (size_t)l * T_TOW * MIN_DIM * FI);
        k_wb2<<<(HCK * HCN + 255) / 256, 256>>>(
            post_W + (size_t)l * T_TOW * OUT_DIM * FO,
            lin_W + l * POST_DIM * FI);
        k_bias2<<<1, 128>>>(post_b + l * POST_DIM,
                            lin_W + l * POST_DIM * FI, lin_b + l * FI);
        k_bnzero<<<1, 128>>>();

        k_gemm_msg<<<dim3(3, N_EDGES / 128), 256>>>(pre_b + l * MSG_DIM);
        k_agg<<<N_NODES, 384>>>();
        k_gemm_hc<<<dim3(2, (N_NODES + 127) / 128), 256>>>();
        k_combine<<<N_NODES / 100, 256>>>();
        k_bn<<<(N_NODES * FI + 255) / 256, 256>>>(bn_g + l * FI, bn_b + l * FI);
    }

    k_poolzero<<<(N_GRAPHS * FI + 255) / 256, 256>>>();
    k_pool<<<(N_NODES * FI + 255) / 256, 256>>>(batch);
    k_mlp<<<N_GRAPHS, 128>>>(mlp_W1, mlp_b1, mlp_W2, mlp_b2, mlp_W3, mlp_b3, out);
}

// round 5
// speedup vs baseline: 2.1799x; 2.1799x over previous
#include <cuda_runtime.h>
#include <math.h>
#include <stdint.h>

#define N_NODES 10000
#define N_EDGES 160000
#define N_GRAPHS 64
#define T_TOW 5
#define FI 75
#define FO 15
#define N_LAYERS 4
#define MSG_DIM 375        // T*FI
#define MIN_DIM 225        // 3*FI
#define OUT_DIM 975        // 13*FI
#define POST_DIM 75        // T*FO
#define HCK 1600           // padded K for hc GEMM (1500 agg + 75 h + 25 pad)
#define HCN 225            // 3*75 output cols (raw | amp | att)
#define AVG_DEG_LOG 2.8332133440562162f

// ---------------- scratch ----------------------------------------------------
__device__ float d_h[N_NODES * FI];
__device__ float d_hc[N_NODES * FI];
__device__ float d_P[N_NODES * 750];               // [P1(+bias) | P2] per node
__device__ float d_P3[16 * MSG_DIM];               // enc @ W3 per combo
__device__ float d_agg[N_NODES * T_TOW * 4 * FI];  // [N,1500] contiguous
__device__ float d_G[N_NODES * HCN];               // hc GEMM output [N,225]
__device__ float d_Wt[MIN_DIM * MSG_DIM];          // pre_W[l] transposed [225,375]
__device__ float d_WB2[HCK * HCN];                 // hc GEMM B matrix [1600,225]
__device__ float d_bias2[FI];
__device__ float d_enctab[16 * FI];
__device__ int   d_cnt[N_NODES];
__device__ int   d_rowstart[N_NODES + 1];
__device__ int   d_cursor[N_NODES];
__device__ int   d_src_csr[N_EDGES];
__device__ int   d_combo_csr[N_EDGES];
__device__ float d_bnsum[FI];
__device__ float d_bnsq[FI];
__device__ float d_pool[N_GRAPHS * FI];

__device__ __forceinline__ float tf32r(float v) {
    uint32_t o;
    asm("cvt.rna.tf32.f32 %0, %1;" : "=r"(o) : "f"(v));
    return __uint_as_float(o);
}

__device__ __forceinline__ void mma_tf32(float* c, const uint32_t* a, const uint32_t* b) {
    asm volatile(
        "mma.sync.aligned.m16n8k8.row.col.f32.tf32.tf32.f32 "
        "{%0,%1,%2,%3}, {%4,%5,%6,%7}, {%8,%9}, {%0,%1,%2,%3};"
        : "+f"(c[0]), "+f"(c[1]), "+f"(c[2]), "+f"(c[3])
        : "r"(a[0]), "r"(a[1]), "r"(a[2]), "r"(a[3]), "r"(b[0]), "r"(b[1]));
}

// ---------------- h0 ----------------------------------------------------------
__global__ void k_h0(const int* __restrict__ x, const float* __restrict__ node_emb,
                     const float* __restrict__ W, const float* __restrict__ b) {
    int idx = blockIdx.x * blockDim.x + threadIdx.x;
    if (idx >= N_NODES * FI) return;
    int n = idx / FI, f = idx % FI;
    int i0 = x[n * 2 + 0], i1 = x[n * 2 + 1];
    const float* e0 = node_emb + i0 * FI;
    const float* e1 = node_emb + i1 * FI;
    float acc = b[f];
    #pragma unroll 5
    for (int c = 0; c < FI; c++) acc += e0[c] * W[c * FI + f];
    #pragma unroll 5
    for (int c = 0; c < FI; c++) acc += e1[c] * W[(FI + c) * FI + f];
    d_h[idx] = acc;
}

// ---------------- CSR build ---------------------------------------------------
__global__ void k_zero_cnt() {
    int i = blockIdx.x * blockDim.x + threadIdx.x;
    if (i < N_NODES) d_cnt[i] = 0;
}

__global__ void k_count(const int* __restrict__ edge_index) {
    int e = blockIdx.x * blockDim.x + threadIdx.x;
    if (e >= N_EDGES) return;
    atomicAdd(&d_cnt[edge_index[N_EDGES + e]], 1);
}

__global__ void k_scan() {
    __shared__ int ssum[1024];
    int tid = threadIdx.x;
    const int ITEMS = 10;
    int base = tid * ITEMS;
    int local[ITEMS];
    int s = 0;
    #pragma unroll
    for (int i = 0; i < ITEMS; i++) {
        int g = base + i;
        int v = (g < N_NODES) ? d_cnt[g] : 0;
        local[i] = s;
        s += v;
    }
    ssum[tid] = s;
    __syncthreads();
    for (int off = 1; off < 1024; off <<= 1) {
        int v = (tid >= off) ? ssum[tid - off] : 0;
        __syncthreads();
        ssum[tid] += v;
        __syncthreads();
    }
    int excl = (tid == 0) ? 0 : ssum[tid - 1];
    #pragma unroll
    for (int i = 0; i < ITEMS; i++) {
        int g = base + i;
        if (g < N_NODES) {
            int rs = excl + local[i];
            d_rowstart[g] = rs;
            d_cursor[g]   = rs;
        }
    }
    if (tid == 0) d_rowstart[N_NODES] = ssum[1023];
}

__global__ void k_fill(const int* __restrict__ edge_index, const int* __restrict__ edge_attr) {
    int e = blockIdx.x * blockDim.x + threadIdx.x;
    if (e >= N_EDGES) return;
    int dst = edge_index[N_EDGES + e];
    int pos = atomicAdd(&d_cursor[dst], 1);
    d_src_csr[pos]   = edge_index[e];
    d_combo_csr[pos] = edge_attr[e * 2] * 4 + edge_attr[e * 2 + 1];
}

// ---------------- per-layer prep ------------------------------------------------
__global__ void k_enctab(const float* __restrict__ edge_emb,
                         const float* __restrict__ encW, const float* __restrict__ encb) {
    int idx = blockIdx.x * blockDim.x + threadIdx.x;
    if (idx >= 16 * FI) return;
    int combo = idx / FI, f = idx % FI;
    int a0 = combo >> 2, a1 = combo & 3;
    const float* e0 = edge_emb + a0 * 25;
    const float* e1 = edge_emb + a1 * 25;
    float acc = encb[f];
    #pragma unroll 5
    for (int q = 0; q < 25; q++) acc += e0[q] * encW[q * FI + f];
    #pragma unroll 5
    for (int q = 0; q < 25; q++) acc += e1[q] * encW[(25 + q) * FI + f];
    d_enctab[idx] = acc;
}

__global__ void k_transpose(const float* __restrict__ preW) {
    int idx = blockIdx.x * blockDim.x + threadIdx.x;
    if (idx >= MIN_DIM * MSG_DIM) return;
    int c = idx / MSG_DIM, j = idx % MSG_DIM;
    int t = j / FI, f = j % FI;
    d_Wt[idx] = preW[(t * MIN_DIM + c) * FI + f];
}

// P3[combo, j] = sum_k enctab[combo,k] * Wt[150+k, j]
__global__ void k_p3() {
    int idx = blockIdx.x * blockDim.x + threadIdx.x;
    if (idx >= 16 * MSG_DIM) return;
    int combo = idx / MSG_DIM, j = idx % MSG_DIM;
    const float* e = d_enctab + combo * FI;
    float acc = 0.f;
    #pragma unroll 5
    for (int k = 0; k < FI; k++) acc += e[k] * d_Wt[(2 * FI + k) * MSG_DIM + j];
    d_P3[idx] = acc;
}

// Build d_WB2[1600,225]
__global__ void k_wb2(const float* __restrict__ postW, const float* __restrict__ linW) {
    int idx = blockIdx.x * blockDim.x + threadIdx.x;
    if (idx >= HCK * HCN) return;
    int k = idx / HCN, j = idx % HCN;
    float acc = 0.f;
    if (k < 1500) {
        int t = k / 300, k300 = k % 300;
        int sel = j / FI, jj = j % FI;
        int c = FI + sel * 300 + k300;
        const float* pw = postW + ((size_t)t * OUT_DIM + c) * FO;
        const float* lw = linW + (t * FO) * FI + jj;
        #pragma unroll
        for (int f = 0; f < FO; f++) acc += pw[f] * lw[f * FI];
    } else if (k < 1575 && j < FI) {
        int c = k - 1500;
        #pragma unroll
        for (int t = 0; t < T_TOW; t++) {
            const float* pw = postW + ((size_t)t * OUT_DIM + c) * FO;
            const float* lw = linW + (t * FO) * FI + j;
            #pragma unroll
            for (int f = 0; f < FO; f++) acc += pw[f] * lw[f * FI];
        }
    }
    d_WB2[idx] = acc;
}

__global__ void k_bias2(const float* __restrict__ postb, const float* __restrict__ linW,
                        const float* __restrict__ linb) {
    int j = threadIdx.x;
    if (j >= FI) return;
    float acc = linb[j];
    #pragma unroll 5
    for (int q = 0; q < T_TOW * FO; q++) acc += postb[q] * linW[q * FI + j];
    d_bias2[j] = acc;
}

__global__ void k_bnzero() {
    int i = threadIdx.x;
    if (i < FI) { d_bnsum[i] = 0.f; d_bnsq[i] = 0.f; }
}

// ---------------- P GEMM: P[10000,750] = h[10000,75] @ [W1|W2] + [bias|0] -------
__global__ void __launch_bounds__(256, 2) k_gemm_p(const float* __restrict__ bias) {
    const int AS = 84, BS = 136;
    __shared__ float As[128 * AS];
    __shared__ float Bs[80 * BS];
    int tid = threadIdx.x;
    int row0 = blockIdx.y * 128;
    int col0 = blockIdx.x * 128;
    int lane = tid & 31, warp = tid >> 5;
    int wm = (warp >> 2) * 64, wn = (warp & 3) * 32;
    int g = lane >> 2, tc = lane & 3;

    // A fill: 128 x 80
    #pragma unroll
    for (int i = 0; i < 40; i++) {
        int idx = i * 256 + tid;
        int r = idx / 80, c = idx - r * 80;
        int grow = row0 + r;
        float v = (grow < N_NODES && c < FI) ? d_h[grow * FI + c] : 0.f;
        As[r * AS + c] = tf32r(v);
    }
    // B fill: 80 x 128 (WP[k][j] = j<375 ? Wt[k][j] : Wt[75+k][j-375])
    #pragma unroll
    for (int i = 0; i < 40; i++) {
        int idx = i * 256 + tid;
        int kr = idx >> 7, c = idx & 127;
        int j = col0 + c;
        float v = 0.f;
        if (kr < FI && j < 750)
            v = (j < MSG_DIM) ? d_Wt[kr * MSG_DIM + j] : d_Wt[(FI + kr) * MSG_DIM + (j - MSG_DIM)];
        Bs[kr * BS + c] = tf32r(v);
    }
    __syncthreads();

    float acc[4][4][4];
    #pragma unroll
    for (int i = 0; i < 4; i++)
        #pragma unroll
        for (int j = 0; j < 4; j++)
            #pragma unroll
            for (int q = 0; q < 4; q++) acc[i][j][q] = 0.f;

    #pragma unroll
    for (int kk = 0; kk < 80; kk += 8) {
        uint32_t a[4][4], b[4][2];
        #pragma unroll
        for (int i = 0; i < 4; i++) {
            int m = wm + i * 16 + g;
            a[i][0] = __float_as_uint(As[m * AS + kk + tc]);
            a[i][1] = __float_as_uint(As[(m + 8) * AS + kk + tc]);
            a[i][2] = __float_as_uint(As[m * AS + kk + tc + 4]);
            a[i][3] = __float_as_uint(As[(m + 8) * AS + kk + tc + 4]);
        }
        #pragma unroll
        for (int j = 0; j < 4; j++) {
            int n = wn + j * 8 + g;
            b[j][0] = __float_as_uint(Bs[(kk + tc) * BS + n]);
            b[j][1] = __float_as_uint(Bs[(kk + tc + 4) * BS + n]);
        }
        #pragma unroll
        for (int i = 0; i < 4; i++)
            #pragma unroll
            for (int j = 0; j < 4; j++) mma_tf32(acc[i][j], a[i], b[j]);
    }

    #pragma unroll
    for (int i = 0; i < 4; i++) {
        int r = row0 + wm + i * 16 + g;
        #pragma unroll
        for (int j = 0; j < 4; j++) {
            int cb = col0 + wn + j * 8 + 2 * tc;
            if (cb < 750) {
                float b0 = (cb < MSG_DIM) ? bias[cb] : 0.f;
                float b1 = (cb + 1 < MSG_DIM) ? bias[cb + 1] : 0.f;
                if (r < N_NODES) {
                    d_P[(size_t)r * 750 + cb] = acc[i][j][0] + b0;
                    if (cb + 1 < 750) d_P[(size_t)r * 750 + cb + 1] = acc[i][j][1] + b1;
                }
                if (r + 8 < N_NODES) {
                    d_P[(size_t)(r + 8) * 750 + cb] = acc[i][j][2] + b0;
                    if (cb + 1 < 750) d_P[(size_t)(r + 8) * 750 + cb + 1] = acc[i][j][3] + b1;
                }
            }
        }
    }
}

// ---------------- fused message + aggregation ----------------------------------
// msg(e,j) = P1[n,j] + P2[src_e,j] + P3[combo_e,j];  accumulate mean/min/max/std
__global__ void k_agg_fused() {
    int n = blockIdx.x;
    int j = threadIdx.x;
    if (j >= MSG_DIM) return;
    int s0 = d_rowstart[n], s1 = d_rowstart[n + 1];
    float p1 = d_P[(size_t)n * 750 + j];
    float s = 0.f, sq = 0.f, mn = 3.4e38f, mx = -3.4e38f;
    for (int i = s0; i < s1; i++) {
        int src = d_src_csr[i];
        int combo = d_combo_csr[i];
        float v = p1 + d_P[(size_t)src * 750 + MSG_DIM + j] + d_P3[combo * MSG_DIM + j];
        s += v; sq += v * v;
        mn = fminf(mn, v); mx = fmaxf(mx, v);
    }
    float cnt = (float)(s1 - s0);
    float deg = fmaxf(cnt, 1.f);
    float mean = s / deg;
    float var = sq / deg - mean * mean;
    if (var < 0.f) var = 0.f;
    float stdv = sqrtf(var + 1e-5f);
    if (s1 == s0) { mn = 0.f; mx = 0.f; }
    int t = j / FI, f = j % FI;
    float* a = d_agg + (size_t)n * (T_TOW * 4 * FI) + t * (4 * FI);
    a[f]          = mean;
    a[FI + f]     = mn;
    a[2 * FI + f] = mx;
    a[3 * FI + f] = stdv;
}

// ---------------- hc GEMM: G[10000,225] = A'[10000,1600] @ WB2 --------------------
// A'[n,c] = c<1500 ? agg[n,c] : (c<1575 ? h[n,c-1500] : 0).  BM=64 -> 314 blocks.
__global__ void __launch_bounds__(256, 2) k_gemm_hc() {
    const int AS = 84, BS = 136;
    __shared__ float As[64 * AS];
    __shared__ float Bs[80 * BS];
    int tid = threadIdx.x;
    int row0 = blockIdx.y * 64;
    int col0 = blockIdx.x * 128;
    int lane = tid & 31, warp = tid >> 5;
    int wm = (warp >> 2) * 32, wn = (warp & 3) * 32;
    int g = lane >> 2, tc = lane & 3;

    float acc[2][4][4];
    #pragma unroll
    for (int i = 0; i < 2; i++)
        #pragma unroll
        for (int j = 0; j < 4; j++)
            #pragma unroll
            for (int q = 0; q < 4; q++) acc[i][j][q] = 0.f;

    for (int k0 = 0; k0 < HCK; k0 += 80) {
        // A fill: 64 x 80 = 5120
        #pragma unroll
        for (int i = 0; i < 20; i++) {
            int idx = i * 256 + tid;
            int r = idx / 80, c = idx - r * 80;
            int grow = row0 + r;
            int gc = k0 + c;
            float v = 0.f;
            if (grow < N_NODES) {
                if (gc < 1500) v = d_agg[(size_t)grow * 1500 + gc];
                else if (gc < 1575) v = d_h[grow * FI + (gc - 1500)];
            }
            As[r * AS + c] = tf32r(v);
        }
        // B fill: 80 x 128
        #pragma unroll
        for (int i = 0; i < 40; i++) {
            int idx = i * 256 + tid;
            int kr = idx >> 7, c = idx & 127;
            int j = col0 + c;
            float v = (j < HCN) ? d_WB2[(size_t)(k0 + kr) * HCN + j] : 0.f;
            Bs[kr * BS + c] = tf32r(v);
        }
        __syncthreads();
        #pragma unroll
        for (int kk = 0; kk < 80; kk += 8) {
            uint32_t a[2][4], b[4][2];
            #pragma unroll
            for (int i = 0; i < 2; i++) {
                int m = wm + i * 16 + g;
                a[i][0] = __float_as_uint(As[m * AS + kk + tc]);
                a[i][1] = __float_as_uint(As[(m + 8) * AS + kk + tc]);
                a[i][2] = __float_as_uint(As[m * AS + kk + tc + 4]);
                a[i][3] = __float_as_uint(As[(m + 8) * AS + kk + tc + 4]);
            }
            #pragma unroll
            for (int j = 0; j < 4; j++) {
                int n = wn + j * 8 + g;
                b[j][0] = __float_as_uint(Bs[(kk + tc) * BS + n]);
                b[j][1] = __float_as_uint(Bs[(kk + tc + 4) * BS + n]);
            }
            #pragma unroll
            for (int i = 0; i < 2; i++)
                #pragma unroll
                for (int j = 0; j < 4; j++) mma_tf32(acc[i][j], a[i], b[j]);
        }
        __syncthreads();
    }

    #pragma unroll
    for (int i = 0; i < 2; i++) {
        int r = row0 + wm + i * 16 + g;
        #pragma unroll
        for (int j = 0; j < 4; j++) {
            int cb = col0 + wn + j * 8 + 2 * tc;
            if (cb < HCN) {
                if (r < N_NODES) {
                    d_G[(size_t)r * HCN + cb] = acc[i][j][0];
                    if (cb + 1 < HCN) d_G[(size_t)r * HCN + cb + 1] = acc[i][j][1];
                }
                if (r + 8 < N_NODES) {
                    d_G[(size_t)(r + 8) * HCN + cb] = acc[i][j][2];
                    if (cb + 1 < HCN) d_G[(size_t)(r + 8) * HCN + cb + 1] = acc[i][j][3];
                }
            }
        }
    }
}

// ---------------- combine G -> hc + BN stats --------------------------------------
__global__ void k_combine() {
    __shared__ float ssum[FI], ssq[FI];
    int tid = threadIdx.x;
    if (tid < FI) { ssum[tid] = 0.f; ssq[tid] = 0.f; }
    __syncthreads();
    int base = blockIdx.x * 100;
    for (int idx = tid; idx < 100 * FI; idx += blockDim.x) {
        int n = base + idx / FI, f = idx % FI;
        float cnt = (float)(d_rowstart[n + 1] - d_rowstart[n]);
        float log_deg = logf(fmaxf(cnt, 1.f) + 1.f);
        float amp = log_deg / AVG_DEG_LOG;
        float att = AVG_DEG_LOG / log_deg;
        const float* gr = d_G + (size_t)n * HCN;
        float v = gr[f] + amp * gr[FI + f] + att * gr[2 * FI + f] + d_bias2[f];
        d_hc[n * FI + f] = v;
        atomicAdd(&ssum[f], v);
        atomicAdd(&ssq[f], v * v);
    }
    __syncthreads();
    if (tid < FI) {
        atomicAdd(&d_bnsum[tid], ssum[tid]);
        atomicAdd(&d_bnsq[tid], ssq[tid]);
    }
}

__global__ void k_bn(const float* __restrict__ g, const float* __restrict__ b) {
    int idx = blockIdx.x * blockDim.x + threadIdx.x;
    if (idx >= N_NODES * FI) return;
    int f = idx % FI;
    float mu = d_bnsum[f] / (float)N_NODES;
    float var = d_bnsq[f] / (float)N_NODES - mu * mu;
    float v = (d_hc[idx] - mu) * rsqrtf(var + 1e-5f) * g[f] + b[f];
    d_h[idx] = fmaxf(v, 0.f);
}

// ---------------- pool + MLP -----------------------------------------------------
__global__ void k_poolzero() {
    int i = blockIdx.x * blockDim.x + threadIdx.x;
    if (i < N_GRAPHS * FI) d_pool[i] = 0.f;
}

__global__ void k_pool(const int* __restrict__ batch) {
    int idx = blockIdx.x * blockDim.x + threadIdx.x;
    if (idx >= N_NODES * FI) return;
    int n = idx / FI, f = idx % FI;
    atomicAdd(&d_pool[batch[n] * FI + f], d_h[idx]);
}

__global__ void k_mlp(const float* __restrict__ W1, const float* __restrict__ b1,
                      const float* __restrict__ W2, const float* __restrict__ b2,
                      const float* __restrict__ W3, const float* __restrict__ b3,
                      float* __restrict__ out) {
    __shared__ float g[FI], h1[50], h2[25];
    int gi = blockIdx.x;
    int tid = threadIdx.x;
    if (tid < FI) g[tid] = d_pool[gi * FI + tid];
    __syncthreads();
    if (tid < 50) {
        float a = b1[tid];
        for (int c = 0; c < FI; c++) a += g[c] * W1[c * 50 + tid];
        h1[tid] = fmaxf(a, 0.f);
    }
    __syncthreads();
    if (tid < 25) {
        float a = b2[tid];
        for (int c = 0; c < 50; c++) a += h1[c] * W2[c * 25 + tid];
        h2[tid] = fmaxf(a, 0.f);
    }
    __syncthreads();
    if (tid == 0) {
        float a = b3[0];
        for (int c = 0; c < 25; c++) a += h2[c] * W3[c];
        out[gi] = a;
    }
}

// ---------------- launch -----------------------------------------------------------
extern "C" void kernel_launch(void* const* d_in, const int* in_sizes, int n_in,
                              void* d_out, int out_size) {
    const int*   x          = (const int*)d_in[0];
    const int*   edge_index = (const int*)d_in[1];
    const int*   edge_attr  = (const int*)d_in[2];
    const int*   batch      = (const int*)d_in[3];
    const float* node_emb   = (const float*)d_in[4];
    const float* edge_emb   = (const float*)d_in[5];
    const float* pre_lin_W  = (const float*)d_in[6];
    const float* pre_lin_b  = (const float*)d_in[7];
    const float* edge_enc_W = (const float*)d_in[8];
    const float* edge_enc_b = (const float*)d_in[9];
    const float* pre_W      = (const float*)d_in[10];
    const float* pre_b      = (const float*)d_in[11];
    const float* post_W     = (const float*)d_in[12];
    const float* post_b     = (const float*)d_in[13];
    const float* lin_W      = (const float*)d_in[14];
    const float* lin_b      = (const float*)d_in[15];
    const float* bn_g       = (const float*)d_in[16];
    const float* bn_b       = (const float*)d_in[17];
    const float* mlp_W1     = (const float*)d_in[18];
    const float* mlp_b1     = (const float*)d_in[19];
    const float* mlp_W2     = (const float*)d_in[20];
    const float* mlp_b2     = (const float*)d_in[21];
    const float* mlp_W3     = (const float*)d_in[22];
    const float* mlp_b3     = (const float*)d_in[23];
    float* out = (float*)d_out;

    k_h0<<<(N_NODES * FI + 255) / 256, 256>>>(x, node_emb, pre_lin_W, pre_lin_b);

    k_zero_cnt<<<(N_NODES + 255) / 256, 256>>>();
    k_count<<<(N_EDGES + 255) / 256, 256>>>(edge_index);
    k_scan<<<1, 1024>>>();
    k_fill<<<(N_EDGES + 255) / 256, 256>>>(edge_index, edge_attr);

    for (int l = 0; l < N_LAYERS; l++) {
        k_enctab<<<(16 * FI + 255) / 256, 256>>>(edge_emb,
            edge_enc_W + l * 50 * FI, edge_enc_b + l * FI);
        k_transpose<<<(MIN_DIM * MSG_DIM + 255) / 256, 256>>>(
            pre_W + (size_t)l * T_TOW * MIN_DIM * FI);
        k_p3<<<(16 * MSG_DIM + 255) / 256, 256>>>();
        k_wb2<<<(HCK * HCN + 255) / 256, 256>>>(
            post_W + (size_t)l * T_TOW * OUT_DIM * FO,
            lin_W + l * POST_DIM * FI);
        k_bias2<<<1, 128>>>(post_b + l * POST_DIM,
                            lin_W + l * POST_DIM * FI, lin_b + l * FI);
        k_bnzero<<<1, 128>>>();

        k_gemm_p<<<dim3(6, (N_NODES + 127) / 128), 256>>>(pre_b + l * MSG_DIM);
        k_agg_fused<<<N_NODES, 384>>>();
        k_gemm_hc<<<dim3(2, (N_NODES + 63) / 64), 256>>>();
        k_combine<<<N_NODES / 100, 256>>>();
        k_bn<<<(N_NODES * FI + 255) / 256, 256>>>(bn_g + l * FI, bn_b + l * FI);
    }

    k_poolzero<<<(N_GRAPHS * FI + 255) / 256, 256>>>();
    k_pool<<<(N_NODES * FI + 255) / 256, 256>>>(batch);
    k_mlp<<<N_GRAPHS, 128>>>(mlp_W1, mlp_b1, mlp_W2, mlp_b2, mlp_W3, mlp_b3, out);
}

// round 7
// speedup vs baseline: 2.5326x; 1.1618x over previous
#include <cuda_runtime.h>
#include <math.h>
#include <stdint.h>

#define N_NODES 10000
#define N_EDGES 160000
#define N_GRAPHS 64
#define T_TOW 5
#define FI 75
#define FO 15
#define N_LAYERS 4
#define MSG_DIM 375        // T*FI
#define MIN_DIM 225        // 3*FI
#define OUT_DIM 975        // 13*FI
#define POST_DIM 75        // T*FO
#define HCK 1600           // padded K for hc GEMM
#define HCK2 800           // split-K half
#define HCN 225            // raw | amp | att
#define AVG_DEG_LOG 2.8332133440562162f

// ---------------- scratch (device-side access only!) ---------------------------
__device__ float d_h[N_NODES * FI];
__device__ float d_hc[N_NODES * FI];
__device__ float d_P[N_NODES * 750];                   // [P1(+bias) | P2]
__device__ float d_agg[N_NODES * 1500];
__device__ float d_G0[N_NODES * HCN];
__device__ float d_G1[N_NODES * HCN];
__device__ float d_Wt[N_LAYERS * MIN_DIM * MSG_DIM];
__device__ float d_WB2[N_LAYERS * HCK * HCN];
__device__ float d_P3[N_LAYERS * 16 * MSG_DIM];
__device__ float d_enctab[N_LAYERS * 16 * FI];
__device__ float d_bias2[N_LAYERS * FI];
__device__ int   d_cnt[N_NODES];
__device__ int   d_rowstart[N_NODES + 1];
__device__ int   d_cursor[N_NODES];
__device__ int   d_src_csr[N_EDGES];
__device__ int   d_combo_csr[N_EDGES];
__device__ float d_bnsum[N_LAYERS * FI];
__device__ float d_bnsq[N_LAYERS * FI];
__device__ float d_pool[N_GRAPHS * FI];

__device__ __forceinline__ float tf32r(float v) {
    uint32_t o;
    asm("cvt.rna.tf32.f32 %0, %1;" : "=r"(o) : "f"(v));
    return __uint_as_float(o);
}

__device__ __forceinline__ void mma_tf32(float* c, const uint32_t* a, const uint32_t* b) {
    asm volatile(
        "mma.sync.aligned.m16n8k8.row.col.f32.tf32.tf32.f32 "
        "{%0,%1,%2,%3}, {%4,%5,%6,%7}, {%8,%9}, {%0,%1,%2,%3};"
        : "+f"(c[0]), "+f"(c[1]), "+f"(c[2]), "+f"(c[3])
        : "r"(a[0]), "r"(a[1]), "r"(a[2]), "r"(a[3]), "r"(b[0]), "r"(b[1]));
}

// ---------------- h0 ----------------------------------------------------------
__global__ void k_h0(const int* __restrict__ x, const float* __restrict__ node_emb,
                     const float* __restrict__ W, const float* __restrict__ b) {
    int idx = blockIdx.x * blockDim.x + threadIdx.x;
    if (idx >= N_NODES * FI) return;
    int n = idx / FI, f = idx % FI;
    int i0 = x[n * 2 + 0], i1 = x[n * 2 + 1];
    const float* e0 = node_emb + i0 * FI;
    const float* e1 = node_emb + i1 * FI;
    float acc = b[f];
    #pragma unroll 5
    for (int c = 0; c < FI; c++) acc += e0[c] * W[c * FI + f];
    #pragma unroll 5
    for (int c = 0; c < FI; c++) acc += e1[c] * W[(FI + c) * FI + f];
    d_h[idx] = acc;
}

// ---------------- CSR build ----------------------------------------------------
__global__ void k_zero_cnt() {
    int i = blockIdx.x * blockDim.x + threadIdx.x;
    if (i < N_NODES) d_cnt[i] = 0;
}

__global__ void k_count(const int* __restrict__ edge_index) {
    int e = blockIdx.x * blockDim.x + threadIdx.x;
    if (e >= N_EDGES) return;
    atomicAdd(&d_cnt[edge_index[N_EDGES + e]], 1);
}

__global__ void k_scan() {
    __shared__ int ssum[1024];
    int tid = threadIdx.x;
    const int ITEMS = 10;
    int base = tid * ITEMS;
    int local[ITEMS];
    int s = 0;
    #pragma unroll
    for (int i = 0; i < ITEMS; i++) {
        int g = base + i;
        int v = (g < N_NODES) ? d_cnt[g] : 0;
        local[i] = s;
        s += v;
    }
    ssum[tid] = s;
    __syncthreads();
    for (int off = 1; off < 1024; off <<= 1) {
        int v = (tid >= off) ? ssum[tid - off] : 0;
        __syncthreads();
        ssum[tid] += v;
        __syncthreads();
    }
    int excl = (tid == 0) ? 0 : ssum[tid - 1];
    #pragma unroll
    for (int i = 0; i < ITEMS; i++) {
        int g = base + i;
        if (g < N_NODES) {
            int rs = excl + local[i];
            d_rowstart[g] = rs;
            d_cursor[g]   = rs;
        }
    }
    if (tid == 0) d_rowstart[N_NODES] = ssum[1023];
}

__global__ void k_fill(const int* __restrict__ edge_index, const int* __restrict__ edge_attr) {
    int e = blockIdx.x * blockDim.x + threadIdx.x;
    if (e >= N_EDGES) return;
    int dst = edge_index[N_EDGES + e];
    int pos = atomicAdd(&d_cursor[dst], 1);
    d_src_csr[pos]   = edge_index[e];
    d_combo_csr[pos] = edge_attr[e * 2] * 4 + edge_attr[e * 2 + 1];
}

// ---------------- all-layer weight prep ------------------------------------------
__global__ void k_transpose_all(const float* __restrict__ preW) {
    int idx = blockIdx.x * blockDim.x + threadIdx.x;
    if (idx >= N_LAYERS * MIN_DIM * MSG_DIM) return;
    int l = idx / (MIN_DIM * MSG_DIM);
    int r = idx % (MIN_DIM * MSG_DIM);
    int c = r / MSG_DIM, j = r % MSG_DIM;
    int t = j / FI, f = j % FI;
    d_Wt[idx] = preW[((size_t)l * T_TOW + t) * MIN_DIM * FI + c * FI + f];
}

__global__ void k_enctab_all(const float* __restrict__ edge_emb,
                             const float* __restrict__ encW, const float* __restrict__ encb) {
    int idx = blockIdx.x * blockDim.x + threadIdx.x;
    if (idx >= N_LAYERS * 16 * FI) return;
    int l = idx / (16 * FI);
    int r = idx % (16 * FI);
    int combo = r / FI, f = r % FI;
    int a0 = combo >> 2, a1 = combo & 3;
    const float* e0 = edge_emb + a0 * 25;
    const float* e1 = edge_emb + a1 * 25;
    const float* W = encW + l * 50 * FI;
    float acc = encb[l * FI + f];
    #pragma unroll 5
    for (int q = 0; q < 25; q++) acc += e0[q] * W[q * FI + f];
    #pragma unroll 5
    for (int q = 0; q < 25; q++) acc += e1[q] * W[(25 + q) * FI + f];
    d_enctab[idx] = acc;
}

__global__ void k_p3_all() {
    int idx = blockIdx.x * blockDim.x + threadIdx.x;
    if (idx >= N_LAYERS * 16 * MSG_DIM) return;
    int l = idx / (16 * MSG_DIM);
    int r = idx % (16 * MSG_DIM);
    int combo = r / MSG_DIM, j = r % MSG_DIM;
    const float* e = d_enctab + (l * 16 + combo) * FI;
    const float* W = d_Wt + (size_t)l * MIN_DIM * MSG_DIM;
    float acc = 0.f;
    #pragma unroll 5
    for (int k = 0; k < FI; k++) acc += e[k] * W[(2 * FI + k) * MSG_DIM + j];
    d_P3[idx] = acc;
}

__global__ void k_wb2_all(const float* __restrict__ postW, const float* __restrict__ linW) {
    int idx = blockIdx.x * blockDim.x + threadIdx.x;
    if (idx >= N_LAYERS * HCK * HCN) return;
    int l = idx / (HCK * HCN);
    int r = idx % (HCK * HCN);
    int k = r / HCN, j = r % HCN;
    const float* pW = postW + (size_t)l * T_TOW * OUT_DIM * FO;
    const float* lW = linW + l * POST_DIM * FI;
    float acc = 0.f;
    if (k < 1500) {
        int t = k / 300, k300 = k % 300;
        int sel = j / FI, jj = j % FI;
        int c = FI + sel * 300 + k300;
        const float* pw = pW + ((size_t)t * OUT_DIM + c) * FO;
        const float* lw = lW + (t * FO) * FI + jj;
        #pragma unroll
        for (int f = 0; f < FO; f++) acc += pw[f] * lw[f * FI];
    } else if (k < 1575 && j < FI) {
        int c = k - 1500;
        #pragma unroll
        for (int t = 0; t < T_TOW; t++) {
            const float* pw = pW + ((size_t)t * OUT_DIM + c) * FO;
            const float* lw = lW + (t * FO) * FI + j;
            #pragma unroll
            for (int f = 0; f < FO; f++) acc += pw[f] * lw[f * FI];
        }
    }
    d_WB2[idx] = acc;
}

__global__ void k_bias2_all(const float* __restrict__ postb, const float* __restrict__ linW,
                            const float* __restrict__ linb) {
    int idx = blockIdx.x * blockDim.x + threadIdx.x;
    if (idx >= N_LAYERS * FI) return;
    int l = idx / FI, j = idx % FI;
    const float* lW = linW + l * POST_DIM * FI;
    float acc = linb[l * FI + j];
    #pragma unroll 5
    for (int q = 0; q < POST_DIM; q++) acc += postb[l * POST_DIM + q] * lW[q * FI + j];
    d_bias2[idx] = acc;
}

__global__ void k_bnzero_all() {
    int i = blockIdx.x * blockDim.x + threadIdx.x;
    if (i < N_LAYERS * FI) { d_bnsum[i] = 0.f; d_bnsq[i] = 0.f; }
    if (i < N_GRAPHS * FI) d_pool[i] = 0.f;
}

// ---------------- P GEMM: P[10000,750] = h @ [W1|W2] + [bias|0] ------------------
__global__ void __launch_bounds__(256, 2) k_gemm_p(int l, const float* __restrict__ bias_all) {
    const int AS = 84, BS = 136;
    __shared__ float As[128 * AS];
    __shared__ float Bs[80 * BS];
    const float* Wt = d_Wt + (size_t)l * MIN_DIM * MSG_DIM;
    const float* bias = bias_all + l * MSG_DIM;
    int tid = threadIdx.x;
    int row0 = blockIdx.y * 128;
    int col0 = blockIdx.x * 128;
    int lane = tid & 31, warp = tid >> 5;
    int wm = (warp >> 2) * 64, wn = (warp & 3) * 32;
    int g = lane >> 2, tc = lane & 3;

    #pragma unroll
    for (int i = 0; i < 40; i++) {
        int idx = i * 256 + tid;
        int r = idx / 80, c = idx - r * 80;
        int grow = row0 + r;
        float v = (grow < N_NODES && c < FI) ? d_h[grow * FI + c] : 0.f;
        As[r * AS + c] = tf32r(v);
    }
    #pragma unroll
    for (int i = 0; i < 40; i++) {
        int idx = i * 256 + tid;
        int kr = idx >> 7, c = idx & 127;
        int j = col0 + c;
        float v = 0.f;
        if (kr < FI && j < 750)
            v = (j < MSG_DIM) ? Wt[kr * MSG_DIM + j] : Wt[(FI + kr) * MSG_DIM + (j - MSG_DIM)];
        Bs[kr * BS + c] = tf32r(v);
    }
    __syncthreads();

    float acc[4][4][4];
    #pragma unroll
    for (int i = 0; i < 4; i++)
        #pragma unroll
        for (int j = 0; j < 4; j++)
            #pragma unroll
            for (int q = 0; q < 4; q++) acc[i][j][q] = 0.f;

    #pragma unroll
    for (int kk = 0; kk < 80; kk += 8) {
        uint32_t a[4][4], b[4][2];
        #pragma unroll
        for (int i = 0; i < 4; i++) {
            int m = wm + i * 16 + g;
            a[i][0] = __float_as_uint(As[m * AS + kk + tc]);
            a[i][1] = __float_as_uint(As[(m + 8) * AS + kk + tc]);
            a[i][2] = __float_as_uint(As[m * AS + kk + tc + 4]);
            a[i][3] = __float_as_uint(As[(m + 8) * AS + kk + tc + 4]);
        }
        #pragma unroll
        for (int j = 0; j < 4; j++) {
            int n = wn + j * 8 + g;
            b[j][0] = __float_as_uint(Bs[(kk + tc) * BS + n]);
            b[j][1] = __float_as_uint(Bs[(kk + tc + 4) * BS + n]);
        }
        #pragma unroll
        for (int i = 0; i < 4; i++)
            #pragma unroll
            for (int j = 0; j < 4; j++) mma_tf32(acc[i][j], a[i], b[j]);
    }

    #pragma unroll
    for (int i = 0; i < 4; i++) {
        int r = row0 + wm + i * 16 + g;
        #pragma unroll
        for (int j = 0; j < 4; j++) {
            int cb = col0 + wn + j * 8 + 2 * tc;
            if (cb < 750) {
                float b0 = (cb < MSG_DIM) ? bias[cb] : 0.f;
                float b1 = (cb + 1 < MSG_DIM) ? bias[cb + 1] : 0.f;
                if (r < N_NODES) {
                    d_P[(size_t)r * 750 + cb] = acc[i][j][0] + b0;
                    if (cb + 1 < 750) d_P[(size_t)r * 750 + cb + 1] = acc[i][j][1] + b1;
                }
                if (r + 8 < N_NODES) {
                    d_P[(size_t)(r + 8) * 750 + cb] = acc[i][j][2] + b0;
                    if (cb + 1 < 750) d_P[(size_t)(r + 8) * 750 + cb + 1] = acc[i][j][3] + b1;
                }
            }
        }
    }
}

// ---------------- fused message + aggregation -------------------------------------
__global__ void k_agg_fused(int l) {
    int n = blockIdx.x;
    int j = threadIdx.x;
    if (j >= MSG_DIM) return;
    const float* P3 = d_P3 + l * 16 * MSG_DIM;
    int s0 = d_rowstart[n], s1 = d_rowstart[n + 1];
    float p1 = d_P[(size_t)n * 750 + j];
    float s = 0.f, sq = 0.f, mn = 3.4e38f, mx = -3.4e38f;
    for (int i = s0; i < s1; i++) {
        int src = d_src_csr[i];
        int combo = d_combo_csr[i];
        float v = p1 + d_P[(size_t)src * 750 + MSG_DIM + j] + P3[combo * MSG_DIM + j];
        s += v; sq += v * v;
        mn = fminf(mn, v); mx = fmaxf(mx, v);
    }
    float cnt = (float)(s1 - s0);
    float deg = fmaxf(cnt, 1.f);
    float mean = s / deg;
    float var = sq / deg - mean * mean;
    if (var < 0.f) var = 0.f;
    float stdv = sqrtf(var + 1e-5f);
    if (s1 == s0) { mn = 0.f; mx = 0.f; }
    int t = j / FI, f = j % FI;
    float* a = d_agg + (size_t)n * 1500 + t * (4 * FI);
    a[f]          = mean;
    a[FI + f]     = mn;
    a[2 * FI + f] = mx;
    a[3 * FI + f] = stdv;
}

// ---------------- hc GEMM (split-K=2) -----------------------------------------------
__global__ void __launch_bounds__(256, 2) k_gemm_hc(int l) {
    const int AS = 84, BS = 136;
    __shared__ float As[64 * AS];
    __shared__ float Bs[80 * BS];
    const float* WB2 = d_WB2 + (size_t)l * HCK * HCN;
    int tid = threadIdx.x;
    int row0 = blockIdx.y * 64;
    int col0 = blockIdx.x * 128;
    int z = blockIdx.z;
    int lane = tid & 31, warp = tid >> 5;
    int wm = (warp >> 2) * 32, wn = (warp & 3) * 32;
    int g = lane >> 2, tc = lane & 3;

    float acc[2][4][4];
    #pragma unroll
    for (int i = 0; i < 2; i++)
        #pragma unroll
        for (int j = 0; j < 4; j++)
            #pragma unroll
            for (int q = 0; q < 4; q++) acc[i][j][q] = 0.f;

    int kbeg = z * HCK2, kend = kbeg + HCK2;
    for (int k0 = kbeg; k0 < kend; k0 += 80) {
        #pragma unroll
        for (int i = 0; i < 20; i++) {
            int idx = i * 256 + tid;
            int r = idx / 80, c = idx - r * 80;
            int grow = row0 + r;
            int gc = k0 + c;
            float v = 0.f;
            if (grow < N_NODES) {
                if (gc < 1500) v = d_agg[(size_t)grow * 1500 + gc];
                else if (gc < 1575) v = d_h[grow * FI + (gc - 1500)];
            }
            As[r * AS + c] = tf32r(v);
        }
        #pragma unroll
        for (int i = 0; i < 40; i++) {
            int idx = i * 256 + tid;
            int kr = idx >> 7, c = idx & 127;
            int j = col0 + c;
            float v = (j < HCN) ? WB2[(size_t)(k0 + kr) * HCN + j] : 0.f;
            Bs[kr * BS + c] = tf32r(v);
        }
        __syncthreads();
        #pragma unroll
        for (int kk = 0; kk < 80; kk += 8) {
            uint32_t a[2][4], b[4][2];
            #pragma unroll
            for (int i = 0; i < 2; i++) {
                int m = wm + i * 16 + g;
                a[i][0] = __float_as_uint(As[m * AS + kk + tc]);
                a[i][1] = __float_as_uint(As[(m + 8) * AS + kk + tc]);
                a[i][2] = __float_as_uint(As[m * AS + kk + tc + 4]);
                a[i][3] = __float_as_uint(As[(m + 8) * AS + kk + tc + 4]);
            }
            #pragma unroll
            for (int j = 0; j < 4; j++) {
                int n = wn + j * 8 + g;
                b[j][0] = __float_as_uint(Bs[(kk + tc) * BS + n]);
                b[j][1] = __float_as_uint(Bs[(kk + tc + 4) * BS + n]);
            }
            #pragma unroll
            for (int i = 0; i < 2; i++)
                #pragma unroll
                for (int j = 0; j < 4; j++) mma_tf32(acc[i][j], a[i], b[j]);
        }
        __syncthreads();
    }

    float* gout = (z == 0) ? d_G0 : d_G1;
    #pragma unroll
    for (int i = 0; i < 2; i++) {
        int r = row0 + wm + i * 16 + g;
        #pragma unroll
        for (int j = 0; j < 4; j++) {
            int cb = col0 + wn + j * 8 + 2 * tc;
            if (cb < HCN) {
                if (r < N_NODES) {
                    gout[(size_t)r * HCN + cb] = acc[i][j][0];
                    if (cb + 1 < HCN) gout[(size_t)r * HCN + cb + 1] = acc[i][j][1];
                }
                if (r + 8 < N_NODES) {
                    gout[(size_t)(r + 8) * HCN + cb] = acc[i][j][2];
                    if (cb + 1 < HCN) gout[(size_t)(r + 8) * HCN + cb + 1] = acc[i][j][3];
                }
            }
        }
    }
}

// ---------------- combine G0+G1 -> hc + BN stats ------------------------------------
__global__ void k_combine(int l) {
    __shared__ float ssum[FI], ssq[FI];
    int tid = threadIdx.x;
    if (tid < FI) { ssum[tid] = 0.f; ssq[tid] = 0.f; }
    __syncthreads();
    const float* bias2 = d_bias2 + l * FI;
    int base = blockIdx.x * 100;
    for (int idx = tid; idx < 100 * FI; idx += blockDim.x) {
        int n = base + idx / FI, f = idx % FI;
        float cnt = (float)(d_rowstart[n + 1] - d_rowstart[n]);
        float log_deg = logf(fmaxf(cnt, 1.f) + 1.f);
        float amp = log_deg / AVG_DEG_LOG;
        float att = AVG_DEG_LOG / log_deg;
        const float* g0 = d_G0 + (size_t)n * HCN;
        const float* g1 = d_G1 + (size_t)n * HCN;
        float v = (g0[f] + g1[f])
                + amp * (g0[FI + f] + g1[FI + f])
                + att * (g0[2 * FI + f] + g1[2 * FI + f]) + bias2[f];
        d_hc[n * FI + f] = v;
        atomicAdd(&ssum[f], v);
        atomicAdd(&ssq[f], v * v);
    }
    __syncthreads();
    if (tid < FI) {
        atomicAdd(&d_bnsum[l * FI + tid], ssum[tid]);
        atomicAdd(&d_bnsq[l * FI + tid], ssq[tid]);
    }
}

__global__ void k_bn(int l, const float* __restrict__ g, const float* __restrict__ b) {
    int idx = blockIdx.x * blockDim.x + threadIdx.x;
    if (idx >= N_NODES * FI) return;
    int f = idx % FI;
    float mu = d_bnsum[l * FI + f] / (float)N_NODES;
    float var = d_bnsq[l * FI + f] / (float)N_NODES - mu * mu;
    float v = (d_hc[idx] - mu) * rsqrtf(var + 1e-5f) * g[f] + b[f];
    d_h[idx] = fmaxf(v, 0.f);
}

// ---------------- pool + MLP ----------------------------------------------------------
__global__ void k_pool(const int* __restrict__ batch) {
    int idx = blockIdx.x * blockDim.x + threadIdx.x;
    if (idx >= N_NODES * FI) return;
    int n = idx / FI, f = idx % FI;
    atomicAdd(&d_pool[batch[n] * FI + f], d_h[idx]);
}

__global__ void k_mlp(const float* __restrict__ W1, const float* __restrict__ b1,
                      const float* __restrict__ W2, const float* __restrict__ b2,
                      const float* __restrict__ W3, const float* __restrict__ b3,
                      float* __restrict__ out) {
    __shared__ float g[FI], h1[50], h2[25];
    int gi = blockIdx.x;
    int tid = threadIdx.x;
    if (tid < FI) g[tid] = d_pool[gi * FI + tid];
    __syncthreads();
    if (tid < 50) {
        float a = b1[tid];
        for (int c = 0; c < FI; c++) a += g[c] * W1[c * 50 + tid];
        h1[tid] = fmaxf(a, 0.f);
    }
    __syncthreads();
    if (tid < 25) {
        float a = b2[tid];
        for (int c = 0; c < 50; c++) a += h1[c] * W2[c * 25 + tid];
        h2[tid] = fmaxf(a, 0.f);
    }
    __syncthreads();
    if (tid == 0) {
        float a = b3[0];
        for (int c = 0; c < 25; c++) a += h2[c] * W3[c];
        out[gi] = a;
    }
}

// ---------------- launch ----------------------------------------------------------------
extern "C" void kernel_launch(void* const* d_in, const int* in_sizes, int n_in,
                              void* d_out, int out_size) {
    const int*   x          = (const int*)d_in[0];
    const int*   edge_index = (const int*)d_in[1];
    const int*   edge_attr  = (const int*)d_in[2];
    const int*   batch      = (const int*)d_in[3];
    const float* node_emb   = (const float*)d_in[4];
    const float* edge_emb   = (const float*)d_in[5];
    const float* pre_lin_W  = (const float*)d_in[6];
    const float* pre_lin_b  = (const float*)d_in[7];
    const float* edge_enc_W = (const float*)d_in[8];
    const float* edge_enc_b = (const float*)d_in[9];
    const float* pre_W      = (const float*)d_in[10];
    const float* pre_b      = (const float*)d_in[11];
    const float* post_W     = (const float*)d_in[12];
    const float* post_b     = (const float*)d_in[13];
    const float* lin_W      = (const float*)d_in[14];
    const float* lin_b      = (const float*)d_in[15];
    const float* bn_g       = (const float*)d_in[16];
    const float* bn_b       = (const float*)d_in[17];
    const float* mlp_W1     = (const float*)d_in[18];
    const float* mlp_b1     = (const float*)d_in[19];
    const float* mlp_W2     = (const float*)d_in[20];
    const float* mlp_b2     = (const float*)d_in[21];
    const float* mlp_W3     = (const float*)d_in[22];
    const float* mlp_b3     = (const float*)d_in[23];
    float* out = (float*)d_out;

    // prologue
    k_transpose_all<<<(N_LAYERS * MIN_DIM * MSG_DIM + 255) / 256, 256>>>(pre_W);
    k_h0<<<(N_NODES * FI + 255) / 256, 256>>>(x, node_emb, pre_lin_W, pre_lin_b);
    k_zero_cnt<<<(N_NODES + 255) / 256, 256>>>();
    k_count<<<(N_EDGES + 255) / 256, 256>>>(edge_index);
    k_scan<<<1, 1024>>>();
    k_gemm_p<<<dim3(6, (N_NODES + 127) / 128), 256>>>(0, pre_b);   // layer 0 P GEMM
    k_fill<<<(N_EDGES + 255) / 256, 256>>>(edge_index, edge_attr);
    k_enctab_all<<<(N_LAYERS * 16 * FI + 255) / 256, 256>>>(edge_emb, edge_enc_W, edge_enc_b);
    k_p3_all<<<(N_LAYERS * 16 * MSG_DIM + 255) / 256, 256>>>();
    k_wb2_all<<<(N_LAYERS * HCK * HCN + 255) / 256, 256>>>(post_W, lin_W);
    k_bias2_all<<<(N_LAYERS * FI + 255) / 256, 256>>>(post_b, lin_W, lin_b);
    k_bnzero_all<<<(N_GRAPHS * FI + 255) / 256, 256>>>();

    for (int l = 0; l < N_LAYERS; l++) {
        if (l > 0) {
            k_gemm_p<<<dim3(6, (N_NODES + 127) / 128), 256>>>(l, pre_b);
        }
        k_agg_fused<<<N_NODES, 384>>>(l);
        k_gemm_hc<<<dim3(2, (N_NODES + 63) / 64, 2), 256>>>(l);
        k_combine<<<N_NODES / 100, 256>>>(l);
        k_bn<<<(N_NODES * FI + 255) / 256, 256>>>(l, bn_g + l * FI, bn_b + l * FI);
    }

    k_pool<<<(N_NODES * FI + 255) / 256, 256>>>(batch);
    k_mlp<<<N_GRAPHS, 128>>>(mlp_W1, mlp_b1, mlp_W2, mlp_b2, mlp_W3, mlp_b3, out);
}

// round 8
// speedup vs baseline: 2.8629x; 1.1304x over previous
#include <cuda_runtime.h>
#include <math.h>
#include <stdint.h>

#define N_NODES 10000
#define N_EDGES 160000
#define N_GRAPHS 64
#define T_TOW 5
#define FI 75
#define FO 15
#define N_LAYERS 4
#define MSG_DIM 375        // T*FI
#define MIN_DIM 225
#define OUT_DIM 975
#define POST_DIM 75
#define PSTRIDE 752        // padded P row: [P1 0..374 | pad | P2 376..750 | pad]
#define P3STRIDE 376
#define HCK 1600
#define HCK2 800
#define HCN 225
#define AVG_DEG_LOG 2.8332133440562162f

// ---------------- scratch (device-side access only) -----------------------------
__device__ float d_h[N_NODES * FI];                // layer-0 input features
__device__ float d_hc[N_NODES * FI];               // pre-BN output of current layer
__device__ float d_P[N_NODES * PSTRIDE];
__device__ float d_agg[N_NODES * 1500];
__device__ float d_G0[N_NODES * HCN];
__device__ float d_G1[N_NODES * HCN];
__device__ float d_Wt[N_LAYERS * MIN_DIM * MSG_DIM];
__device__ float d_WB2[N_LAYERS * HCK * HCN];
__device__ float d_P3[N_LAYERS * 16 * P3STRIDE];
__device__ float d_enctab[N_LAYERS * 16 * FI];
__device__ float d_bias2[N_LAYERS * FI];
__device__ int   d_cnt[N_NODES];
__device__ int   d_rowstart[N_NODES + 1];
__device__ int   d_cursor[N_NODES];
__device__ int   d_src_csr[N_EDGES];
__device__ int   d_combo_csr[N_EDGES];
__device__ float d_bnsum[N_LAYERS * FI];
__device__ float d_bnsq[N_LAYERS * FI];
__device__ float d_bnscale[N_LAYERS * FI];
__device__ float d_bnshift[N_LAYERS * FI];
__device__ float d_pool[N_GRAPHS * FI];

__device__ __forceinline__ float tf32r(float v) {
    uint32_t o;
    asm("cvt.rna.tf32.f32 %0, %1;" : "=r"(o) : "f"(v));
    return __uint_as_float(o);
}

__device__ __forceinline__ void mma_tf32(float* c, const uint32_t* a, const uint32_t* b) {
    asm volatile(
        "mma.sync.aligned.m16n8k8.row.col.f32.tf32.tf32.f32 "
        "{%0,%1,%2,%3}, {%4,%5,%6,%7}, {%8,%9}, {%0,%1,%2,%3};"
        : "+f"(c[0]), "+f"(c[1]), "+f"(c[2]), "+f"(c[3])
        : "r"(a[0]), "r"(a[1]), "r"(a[2]), "r"(a[3]), "r"(b[0]), "r"(b[1]));
}

// h value for layer l input, feature f of node n (BN+ReLU applied on the fly)
__device__ __forceinline__ float hval(int l, int n, int f) {
    if (l == 0) return d_h[n * FI + f];
    int o = (l - 1) * FI + f;
    return fmaxf(d_hc[n * FI + f] * d_bnscale[o] + d_bnshift[o], 0.f);
}

// ---------------- h0 --------------------------------------------------------------
__global__ void k_h0(const int* __restrict__ x, const float* __restrict__ node_emb,
                     const float* __restrict__ W, const float* __restrict__ b) {
    int idx = blockIdx.x * blockDim.x + threadIdx.x;
    if (idx >= N_NODES * FI) return;
    int n = idx / FI, f = idx % FI;
    int i0 = x[n * 2 + 0], i1 = x[n * 2 + 1];
    const float* e0 = node_emb + i0 * FI;
    const float* e1 = node_emb + i1 * FI;
    float acc = b[f];
    #pragma unroll 5
    for (int c = 0; c < FI; c++) acc += e0[c] * W[c * FI + f];
    #pragma unroll 5
    for (int c = 0; c < FI; c++) acc += e1[c] * W[(FI + c) * FI + f];
    d_h[idx] = acc;
}

// ---------------- CSR build --------------------------------------------------------
__global__ void k_zero_cnt() {
    int i = blockIdx.x * blockDim.x + threadIdx.x;
    if (i < N_NODES) d_cnt[i] = 0;
}

__global__ void k_count(const int* __restrict__ edge_index) {
    int e = blockIdx.x * blockDim.x + threadIdx.x;
    if (e >= N_EDGES) return;
    atomicAdd(&d_cnt[edge_index[N_EDGES + e]], 1);
}

__global__ void k_scan() {
    __shared__ int ssum[1024];
    int tid = threadIdx.x;
    const int ITEMS = 10;
    int base = tid * ITEMS;
    int local[ITEMS];
    int s = 0;
    #pragma unroll
    for (int i = 0; i < ITEMS; i++) {
        int g = base + i;
        int v = (g < N_NODES) ? d_cnt[g] : 0;
        local[i] = s;
        s += v;
    }
    ssum[tid] = s;
    __syncthreads();
    for (int off = 1; off < 1024; off <<= 1) {
        int v = (tid >= off) ? ssum[tid - off] : 0;
        __syncthreads();
        ssum[tid] += v;
        __syncthreads();
    }
    int excl = (tid == 0) ? 0 : ssum[tid - 1];
    #pragma unroll
    for (int i = 0; i < ITEMS; i++) {
        int g = base + i;
        if (g < N_NODES) {
            int rs = excl + local[i];
            d_rowstart[g] = rs;
            d_cursor[g]   = rs;
        }
    }
    if (tid == 0) d_rowstart[N_NODES] = ssum[1023];
}

__global__ void k_fill(const int* __restrict__ edge_index, const int* __restrict__ edge_attr) {
    int e = blockIdx.x * blockDim.x + threadIdx.x;
    if (e >= N_EDGES) return;
    int dst = edge_index[N_EDGES + e];
    int pos = atomicAdd(&d_cursor[dst], 1);
    d_src_csr[pos]   = edge_index[e];
    d_combo_csr[pos] = edge_attr[e * 2] * 4 + edge_attr[e * 2 + 1];
}

// ---------------- all-layer weight prep ---------------------------------------------
__global__ void k_transpose_all(const float* __restrict__ preW) {
    int idx = blockIdx.x * blockDim.x + threadIdx.x;
    if (idx >= N_LAYERS * MIN_DIM * MSG_DIM) return;
    int l = idx / (MIN_DIM * MSG_DIM);
    int r = idx % (MIN_DIM * MSG_DIM);
    int c = r / MSG_DIM, j = r % MSG_DIM;
    int t = j / FI, f = j % FI;
    d_Wt[idx] = preW[((size_t)l * T_TOW + t) * MIN_DIM * FI + c * FI + f];
}

__global__ void k_enctab_all(const float* __restrict__ edge_emb,
                             const float* __restrict__ encW, const float* __restrict__ encb) {
    int idx = blockIdx.x * blockDim.x + threadIdx.x;
    if (idx >= N_LAYERS * 16 * FI) return;
    int l = idx / (16 * FI);
    int r = idx % (16 * FI);
    int combo = r / FI, f = r % FI;
    int a0 = combo >> 2, a1 = combo & 3;
    const float* e0 = edge_emb + a0 * 25;
    const float* e1 = edge_emb + a1 * 25;
    const float* W = encW + l * 50 * FI;
    float acc = encb[l * FI + f];
    #pragma unroll 5
    for (int q = 0; q < 25; q++) acc += e0[q] * W[q * FI + f];
    #pragma unroll 5
    for (int q = 0; q < 25; q++) acc += e1[q] * W[(25 + q) * FI + f];
    d_enctab[idx] = acc;
}

__global__ void k_p3_all() {
    int idx = blockIdx.x * blockDim.x + threadIdx.x;
    if (idx >= N_LAYERS * 16 * P3STRIDE) return;
    int l = idx / (16 * P3STRIDE);
    int r = idx % (16 * P3STRIDE);
    int combo = r / P3STRIDE, j = r % P3STRIDE;
    float acc = 0.f;
    if (j < MSG_DIM) {
        const float* e = d_enctab + (l * 16 + combo) * FI;
        const float* W = d_Wt + (size_t)l * MIN_DIM * MSG_DIM;
        #pragma unroll 5
        for (int k = 0; k < FI; k++) acc += e[k] * W[(2 * FI + k) * MSG_DIM + j];
    }
    d_P3[idx] = acc;
}

__global__ void k_wb2_all(const float* __restrict__ postW, const float* __restrict__ linW) {
    int idx = blockIdx.x * blockDim.x + threadIdx.x;
    if (idx >= N_LAYERS * HCK * HCN) return;
    int l = idx / (HCK * HCN);
    int r = idx % (HCK * HCN);
    int k = r / HCN, j = r % HCN;
    const float* pW = postW + (size_t)l * T_TOW * OUT_DIM * FO;
    const float* lW = linW + l * POST_DIM * FI;
    float acc = 0.f;
    if (k < 1500) {
        int t = k / 300, k300 = k % 300;
        int sel = j / FI, jj = j % FI;
        int c = FI + sel * 300 + k300;
        const float* pw = pW + ((size_t)t * OUT_DIM + c) * FO;
        const float* lw = lW + (t * FO) * FI + jj;
        #pragma unroll
        for (int f = 0; f < FO; f++) acc += pw[f] * lw[f * FI];
    } else if (k < 1575 && j < FI) {
        int c = k - 1500;
        #pragma unroll
        for (int t = 0; t < T_TOW; t++) {
            const float* pw = pW + ((size_t)t * OUT_DIM + c) * FO;
            const float* lw = lW + (t * FO) * FI + j;
            #pragma unroll
            for (int f = 0; f < FO; f++) acc += pw[f] * lw[f * FI];
        }
    }
    d_WB2[idx] = acc;
}

__global__ void k_bias2_all(const float* __restrict__ postb, const float* __restrict__ linW,
                            const float* __restrict__ linb) {
    int idx = blockIdx.x * blockDim.x + threadIdx.x;
    if (idx >= N_LAYERS * FI) return;
    int l = idx / FI, j = idx % FI;
    const float* lW = linW + l * POST_DIM * FI;
    float acc = linb[l * FI + j];
    #pragma unroll 5
    for (int q = 0; q < POST_DIM; q++) acc += postb[l * POST_DIM + q] * lW[q * FI + j];
    d_bias2[idx] = acc;
}

__global__ void k_bnzero_all() {
    int i = blockIdx.x * blockDim.x + threadIdx.x;
    if (i < N_LAYERS * FI) { d_bnsum[i] = 0.f; d_bnsq[i] = 0.f; }
    if (i < N_GRAPHS * FI) d_pool[i] = 0.f;
}

// ---------------- P GEMM: P[n] = [h|h] @ [W1|W2] + [bias|0], BN fused on A ---------
__global__ void __launch_bounds__(256, 2) k_gemm_p(int l, const float* __restrict__ bias_all) {
    const int AS = 84, BS = 136;
    __shared__ float As[128 * AS];
    __shared__ float Bs[80 * BS];
    const float* Wt = d_Wt + (size_t)l * MIN_DIM * MSG_DIM;
    const float* bias = bias_all + l * MSG_DIM;
    int tid = threadIdx.x;
    int row0 = blockIdx.y * 128;
    int col0 = blockIdx.x * 128;
    int lane = tid & 31, warp = tid >> 5;
    int wm = (warp >> 2) * 64, wn = (warp & 3) * 32;
    int g = lane >> 2, tc = lane & 3;

    #pragma unroll
    for (int i = 0; i < 40; i++) {
        int idx = i * 256 + tid;
        int r = idx / 80, c = idx - r * 80;
        int grow = row0 + r;
        float v = (grow < N_NODES && c < FI) ? hval(l, grow, c) : 0.f;
        As[r * AS + c] = tf32r(v);
    }
    #pragma unroll
    for (int i = 0; i < 40; i++) {
        int idx = i * 256 + tid;
        int kr = idx >> 7, c = idx & 127;
        int j = col0 + c;
        float v = 0.f;
        if (kr < FI && j < 750)
            v = (j < MSG_DIM) ? Wt[kr * MSG_DIM + j] : Wt[(FI + kr) * MSG_DIM + (j - MSG_DIM)];
        Bs[kr * BS + c] = tf32r(v);
    }
    __syncthreads();

    float acc[4][4][4];
    #pragma unroll
    for (int i = 0; i < 4; i++)
        #pragma unroll
        for (int j = 0; j < 4; j++)
            #pragma unroll
            for (int q = 0; q < 4; q++) acc[i][j][q] = 0.f;

    #pragma unroll
    for (int kk = 0; kk < 80; kk += 8) {
        uint32_t a[4][4], b[4][2];
        #pragma unroll
        for (int i = 0; i < 4; i++) {
            int m = wm + i * 16 + g;
            a[i][0] = __float_as_uint(As[m * AS + kk + tc]);
            a[i][1] = __float_as_uint(As[(m + 8) * AS + kk + tc]);
            a[i][2] = __float_as_uint(As[m * AS + kk + tc + 4]);
            a[i][3] = __float_as_uint(As[(m + 8) * AS + kk + tc + 4]);
        }
        #pragma unroll
        for (int j = 0; j < 4; j++) {
            int n = wn + j * 8 + g;
            b[j][0] = __float_as_uint(Bs[(kk + tc) * BS + n]);
            b[j][1] = __float_as_uint(Bs[(kk + tc + 4) * BS + n]);
        }
        #pragma unroll
        for (int i = 0; i < 4; i++)
            #pragma unroll
            for (int j = 0; j < 4; j++) mma_tf32(acc[i][j], a[i], b[j]);
    }

    #pragma unroll
    for (int i = 0; i < 4; i++) {
        int r = row0 + wm + i * 16 + g;
        #pragma unroll
        for (int j = 0; j < 4; j++) {
            int cb = col0 + wn + j * 8 + 2 * tc;
            if (cb < 750) {
                // P column map: P1 cols [0,375) at offset c; P2 cols at offset c+1 (pad at 375)
                int o0 = (cb < MSG_DIM) ? cb : cb + 1;
                float b0 = (cb < MSG_DIM) ? bias[cb] : 0.f;
                if (r < N_NODES) d_P[(size_t)r * PSTRIDE + o0] = acc[i][j][0] + b0;
                if (r + 8 < N_NODES) d_P[(size_t)(r + 8) * PSTRIDE + o0] = acc[i][j][2] + b0;
                if (cb + 1 < 750) {
                    int o1 = (cb + 1 < MSG_DIM) ? cb + 1 : cb + 2;
                    float b1 = (cb + 1 < MSG_DIM) ? bias[cb + 1] : 0.f;
                    if (r < N_NODES) d_P[(size_t)r * PSTRIDE + o1] = acc[i][j][1] + b1;
                    if (r + 8 < N_NODES) d_P[(size_t)(r + 8) * PSTRIDE + o1] = acc[i][j][3] + b1;
                }
            }
        }
    }
}

// ---------------- fused message + aggregation (float2 gathers) -----------------------
__global__ void k_agg_fused(int l) {
    int n = blockIdx.x;
    int t = threadIdx.x;            // 192 threads, 188 active (2 cols each)
    if (t >= 188) return;
    int j = 2 * t;
    const float2* P3 = (const float2*)(d_P3 + (size_t)l * 16 * P3STRIDE);
    int s0 = d_rowstart[n], s1 = d_rowstart[n + 1];
    float2 p1 = *(const float2*)(d_P + (size_t)n * PSTRIDE + j);
    float sx = 0.f, sy = 0.f, qx = 0.f, qy = 0.f;
    float mnx = 3.4e38f, mny = 3.4e38f, mxx = -3.4e38f, mxy = -3.4e38f;
    for (int i = s0; i < s1; i++) {
        int src = d_src_csr[i];
        int combo = d_combo_csr[i];
        float2 p2 = *(const float2*)(d_P + (size_t)src * PSTRIDE + 376 + j);
        float2 p3 = P3[combo * 188 + t];
        float vx = p1.x + p2.x + p3.x;
        float vy = p1.y + p2.y + p3.y;
        sx += vx; sy += vy;
        qx += vx * vx; qy += vy * vy;
        mnx = fminf(mnx, vx); mny = fminf(mny, vy);
        mxx = fmaxf(mxx, vx); mxy = fmaxf(mxy, vy);
    }
    float cnt = (float)(s1 - s0);
    float deg = fmaxf(cnt, 1.f);
    bool empty = (s1 == s0);
    float* abase = d_agg + (size_t)n * 1500;
    #pragma unroll
    for (int k = 0; k < 2; k++) {
        int jj = j + k;
        if (jj >= MSG_DIM) break;
        float s = k ? sy : sx;
        float q = k ? qy : qx;
        float mn = k ? mny : mnx;
        float mx = k ? mxy : mxx;
        float mean = s / deg;
        float var = q / deg - mean * mean;
        if (var < 0.f) var = 0.f;
        float stdv = sqrtf(var + 1e-5f);
        if (empty) { mn = 0.f; mx = 0.f; }
        int tw = jj / FI, f = jj % FI;
        float* a = abase + tw * (4 * FI);
        a[f]          = mean;
        a[FI + f]     = mn;
        a[2 * FI + f] = mx;
        a[3 * FI + f] = stdv;
    }
}

// ---------------- hc GEMM (split-K=2), BN fused on K-tail ----------------------------
__global__ void __launch_bounds__(256, 2) k_gemm_hc(int l) {
    const int AS = 84, BS = 136;
    __shared__ float As[64 * AS];
    __shared__ float Bs[80 * BS];
    const float* WB2 = d_WB2 + (size_t)l * HCK * HCN;
    int tid = threadIdx.x;
    int row0 = blockIdx.y * 64;
    int col0 = blockIdx.x * 128;
    int z = blockIdx.z;
    int lane = tid & 31, warp = tid >> 5;
    int wm = (warp >> 2) * 32, wn = (warp & 3) * 32;
    int g = lane >> 2, tc = lane & 3;

    float acc[2][4][4];
    #pragma unroll
    for (int i = 0; i < 2; i++)
        #pragma unroll
        for (int j = 0; j < 4; j++)
            #pragma unroll
            for (int q = 0; q < 4; q++) acc[i][j][q] = 0.f;

    int kbeg = z * HCK2, kend = kbeg + HCK2;
    for (int k0 = kbeg; k0 < kend; k0 += 80) {
        #pragma unroll
        for (int i = 0; i < 20; i++) {
            int idx = i * 256 + tid;
            int r = idx / 80, c = idx - r * 80;
            int grow = row0 + r;
            int gc = k0 + c;
            float v = 0.f;
            if (grow < N_NODES) {
                if (gc < 1500) v = d_agg[(size_t)grow * 1500 + gc];
                else if (gc < 1575) v = hval(l, grow, gc - 1500);
            }
            As[r * AS + c] = tf32r(v);
        }
        #pragma unroll
        for (int i = 0; i < 40; i++) {
            int idx = i * 256 + tid;
            int kr = idx >> 7, c = idx & 127;
            int j = col0 + c;
            float v = (j < HCN) ? WB2[(size_t)(k0 + kr) * HCN + j] : 0.f;
            Bs[kr * BS + c] = tf32r(v);
        }
        __syncthreads();
        #pragma unroll
        for (int kk = 0; kk < 80; kk += 8) {
            uint32_t a[2][4], b[4][2];
            #pragma unroll
            for (int i = 0; i < 2; i++) {
                int m = wm + i * 16 + g;
                a[i][0] = __float_as_uint(As[m * AS + kk + tc]);
                a[i][1] = __float_as_uint(As[(m + 8) * AS + kk + tc]);
                a[i][2] = __float_as_uint(As[m * AS + kk + tc + 4]);
                a[i][3] = __float_as_uint(As[(m + 8) * AS + kk + tc + 4]);
            }
            #pragma unroll
            for (int j = 0; j < 4; j++) {
                int n = wn + j * 8 + g;
                b[j][0] = __float_as_uint(Bs[(kk + tc) * BS + n]);
                b[j][1] = __float_as_uint(Bs[(kk + tc + 4) * BS + n]);
            }
            #pragma unroll
            for (int i = 0; i < 2; i++)
                #pragma unroll
                for (int j = 0; j < 4; j++) mma_tf32(acc[i][j], a[i], b[j]);
        }
        __syncthreads();
    }

    float* gout = (z == 0) ? d_G0 : d_G1;
    #pragma unroll
    for (int i = 0; i < 2; i++) {
        int r = row0 + wm + i * 16 + g;
        #pragma unroll
        for (int j = 0; j < 4; j++) {
            int cb = col0 + wn + j * 8 + 2 * tc;
            if (cb < HCN) {
                if (r < N_NODES) {
                    gout[(size_t)r * HCN + cb] = acc[i][j][0];
                    if (cb + 1 < HCN) gout[(size_t)r * HCN + cb + 1] = acc[i][j][1];
                }
                if (r + 8 < N_NODES) {
                    gout[(size_t)(r + 8) * HCN + cb] = acc[i][j][2];
                    if (cb + 1 < HCN) gout[(size_t)(r + 8) * HCN + cb + 1] = acc[i][j][3];
                }
            }
        }
    }
}

// ---------------- combine G0+G1 -> hc + BN stats --------------------------------------
__global__ void k_combine(int l) {
    __shared__ float ssum[FI], ssq[FI];
    int tid = threadIdx.x;
    if (tid < FI) { ssum[tid] = 0.f; ssq[tid] = 0.f; }
    __syncthreads();
    const float* bias2 = d_bias2 + l * FI;
    int base = blockIdx.x * 100;
    for (int idx = tid; idx < 100 * FI; idx += blockDim.x) {
        int n = base + idx / FI, f = idx % FI;
        float cnt = (float)(d_rowstart[n + 1] - d_rowstart[n]);
        float log_deg = logf(fmaxf(cnt, 1.f) + 1.f);
        float amp = log_deg / AVG_DEG_LOG;
        float att = AVG_DEG_LOG / log_deg;
        const float* g0 = d_G0 + (size_t)n * HCN;
        const float* g1 = d_G1 + (size_t)n * HCN;
        float v = (g0[f] + g1[f])
                + amp * (g0[FI + f] + g1[FI + f])
                + att * (g0[2 * FI + f] + g1[2 * FI + f]) + bias2[f];
        d_hc[n * FI + f] = v;
        atomicAdd(&ssum[f], v);
        atomicAdd(&ssq[f], v * v);
    }
    __syncthreads();
    if (tid < FI) {
        atomicAdd(&d_bnsum[l * FI + tid], ssum[tid]);
        atomicAdd(&d_bnsq[l * FI + tid], ssq[tid]);
    }
}

// ---------------- finalize BN scale/shift (1 block) -------------------------------------
__global__ void k_bnfin(int l, const float* __restrict__ g, const float* __restrict__ b) {
    int f = threadIdx.x;
    if (f >= FI) return;
    float mu = d_bnsum[l * FI + f] / (float)N_NODES;
    float var = d_bnsq[l * FI + f] / (float)N_NODES - mu * mu;
    float sc = g[l * FI + f] * rsqrtf(var + 1e-5f);
    d_bnscale[l * FI + f] = sc;
    d_bnshift[l * FI + f] = b[l * FI + f] - mu * sc;
}

// ---------------- pool (BN fused) + MLP ---------------------------------------------------
__global__ void k_pool(const int* __restrict__ batch) {
    int idx = blockIdx.x * blockDim.x + threadIdx.x;
    if (idx >= N_NODES * FI) return;
    int n = idx / FI, f = idx % FI;
    int o = (N_LAYERS - 1) * FI + f;
    float v = fmaxf(d_hc[idx] * d_bnscale[o] + d_bnshift[o], 0.f);
    atomicAdd(&d_pool[batch[n] * FI + f], v);
}

__global__ void k_mlp(const float* __restrict__ W1, const float* __restrict__ b1,
                      const float* __restrict__ W2, const float* __restrict__ b2,
                      const float* __restrict__ W3, const float* __restrict__ b3,
                      float* __restrict__ out) {
    __shared__ float g[FI], h1[50], h2[25];
    int gi = blockIdx.x;
    int tid = threadIdx.x;
    if (tid < FI) g[tid] = d_pool[gi * FI + tid];
    __syncthreads();
    if (tid < 50) {
        float a = b1[tid];
        for (int c = 0; c < FI; c++) a += g[c] * W1[c * 50 + tid];
        h1[tid] = fmaxf(a, 0.f);
    }
    __syncthreads();
    if (tid < 25) {
        float a = b2[tid];
        for (int c = 0; c < 50; c++) a += h1[c] * W2[c * 25 + tid];
        h2[tid] = fmaxf(a, 0.f);
    }
    __syncthreads();
    if (tid == 0) {
        float a = b3[0];
        for (int c = 0; c < 25; c++) a += h2[c] * W3[c];
        out[gi] = a;
    }
}

// ---------------- launch --------------------------------------------------------------------
extern "C" void kernel_launch(void* const* d_in, const int* in_sizes, int n_in,
                              void* d_out, int out_size) {
    const int*   x          = (const int*)d_in[0];
    const int*   edge_index = (const int*)d_in[1];
    const int*   edge_attr  = (const int*)d_in[2];
    const int*   batch      = (const int*)d_in[3];
    const float* node_emb   = (const float*)d_in[4];
    const float* edge_emb   = (const float*)d_in[5];
    const float* pre_lin_W  = (const float*)d_in[6];
    const float* pre_lin_b  = (const float*)d_in[7];
    const float* edge_enc_W = (const float*)d_in[8];
    const float* edge_enc_b = (const float*)d_in[9];
    const float* pre_W      = (const float*)d_in[10];
    const float* pre_b      = (const float*)d_in[11];
    const float* post_W     = (const float*)d_in[12];
    const float* post_b     = (const float*)d_in[13];
    const float* lin_W      = (const float*)d_in[14];
    const float* lin_b      = (const float*)d_in[15];
    const float* bn_g       = (const float*)d_in[16];
    const float* bn_b       = (const float*)d_in[17];
    const float* mlp_W1     = (const float*)d_in[18];
    const float* mlp_b1     = (const float*)d_in[19];
    const float* mlp_W2     = (const float*)d_in[20];
    const float* mlp_b2     = (const float*)d_in[21];
    const float* mlp_W3     = (const float*)d_in[22];
    const float* mlp_b3     = (const float*)d_in[23];
    float* out = (float*)d_out;

    // prologue
    k_transpose_all<<<(N_LAYERS * MIN_DIM * MSG_DIM + 255) / 256, 256>>>(pre_W);
    k_h0<<<(N_NODES * FI + 255) / 256, 256>>>(x, node_emb, pre_lin_W, pre_lin_b);
    k_zero_cnt<<<(N_NODES + 255) / 256, 256>>>();
    k_count<<<(N_EDGES + 255) / 256, 256>>>(edge_index);
    k_scan<<<1, 1024>>>();
    k_gemm_p<<<dim3(6, (N_NODES + 127) / 128), 256>>>(0, pre_b);   // layer-0 P GEMM
    k_fill<<<(N_EDGES + 255) / 256, 256>>>(edge_index, edge_attr);
    k_enctab_all<<<(N_LAYERS * 16 * FI + 255) / 256, 256>>>(edge_emb, edge_enc_W, edge_enc_b);
    k_p3_all<<<(N_LAYERS * 16 * P3STRIDE + 255) / 256, 256>>>();
    k_wb2_all<<<(N_LAYERS * HCK * HCN + 255) / 256, 256>>>(post_W, lin_W);
    k_bias2_all<<<(N_LAYERS * FI + 255) / 256, 256>>>(post_b, lin_W, lin_b);
    k_bnzero_all<<<(N_GRAPHS * FI + 255) / 256, 256>>>();

    for (int l = 0; l < N_LAYERS; l++) {
        if (l > 0) {
            k_gemm_p<<<dim3(6, (N_NODES + 127) / 128), 256>>>(l, pre_b);
        }
        k_agg_fused<<<N_NODES, 192>>>(l);
        k_gemm_hc<<<dim3(2, (N_NODES + 63) / 64, 2), 256>>>(l);
        k_combine<<<N_NODES / 100, 256>>>(l);
        k_bnfin<<<1, 128>>>(l, bn_g, bn_b);
    }

    k_pool<<<(N_NODES * FI + 255) / 256, 256>>>(batch);
    k_mlp<<<N_GRAPHS, 128>>>(mlp_W1, mlp_b1, mlp_W2, mlp_b2, mlp_W3, mlp_b3, out);
}